// round 5
// baseline (speedup 1.0000x reference)
#include <cuda_runtime.h>
#include <cstddef>

#define ED 1024
#define BD 2048
#define BA 128
#define NITER 500
#define LAMB_C 0.3f
#define H_C 0.005f
#define RMC 0.99f
#define LOWACT 0.001f
#define GRID 128
#define BKC 32

#define O_A     ((size_t)0)
#define O_BASIS ((size_t)(BD*BA))
#define O_HES   (O_BASIS + (size_t)ED*BD)
#define O_L1    (O_HES + BD)
#define O_SNR   (O_L1 + BD)

__device__ float g_BT[(size_t)BD*ED];
__device__ float g_It[(size_t)ED*BA];
__device__ float g_a [(size_t)BD*BA];
__device__ float g_r [(size_t)ED*BA];
__device__ float g_S [(size_t)ED*ED];
__device__ float g_T0[(size_t)ED*ED];
__device__ float g_T1[(size_t)ED*ED];
__device__ float g_NB[(size_t)ED*BD];
__device__ float g_hes[BD];
__device__ float g_nsq[BD];
__device__ float g_v[ED];
__device__ float g_w[ED];
__device__ float g_scal[8];             // 0:lam 1:eta 2:thr 3:scale 4:sumI2
__device__ unsigned g_cnt;
__device__ volatile unsigned g_gen;

__device__ __forceinline__ float sshrinkf(float v, float thr) {
    float t = fabsf(v) - thr;
    return t > 0.0f ? copysignf(t, v) : 0.0f;
}

// packed fp32 FMA: d = a*b + d (elementwise on 2 lanes) — rounding identical to fmaf
__device__ __forceinline__ void ffma2(unsigned long long &d, unsigned long long a,
                                      unsigned long long b) {
    asm("fma.rn.f32x2 %0, %1, %2, %0;" : "+l"(d) : "l"(a), "l"(b));
}
__device__ __forceinline__ float2 upk(unsigned long long v) {
    float2 f;
    asm("mov.b64 {%0, %1}, %2;" : "=f"(f.x), "=f"(f.y) : "l"(v));
    return f;
}

// ---- software grid barrier ----
__device__ __forceinline__ void gsync(unsigned gen) {
    __syncthreads();
    if (threadIdx.x == 0) {
        __threadfence();
        unsigned t = atomicAdd(&g_cnt, 1u);
        if (t == GRID - 1) {
            g_cnt = 0;
            __threadfence();
            g_gen = gen;
        } else {
            while (g_gen < gen) { }
            __threadfence();
        }
    }
    __syncthreads();
}

// ---- ROWS x 128 tile GEMM, packed f32x2, BK=32 double-buffered, 128 thr ----
// As holds A values DUPLICATED ({a,a} pairs) so packed operands load directly.
template<int ROWS>
__device__ __forceinline__ void tile_mm2(
    const float* __restrict__ A0, int lda, const float* __restrict__ Bsrc,
    int ktiles,
    float (&As)[2][BKC][40], float (&Bs)[2][BKC][128],
    unsigned long long (&acc)[ROWS/4][2], int tid)
{
    constexpr int RPW = ROWS / 4;      // rows per warp (thread handles RPW rows x 4 cols)
    const int warp = tid >> 5, l = tid & 31;
    float4 ra; float2 ra2; float4 rb[8];

    // prefetch tile 0
    if (ROWS == 16) {
        int m = tid >> 3, kq = (tid & 7) * 4;
        ra = *(const float4*)(A0 + (size_t)m*lda + kq);
    } else {
        int m = tid >> 4, kq = (tid & 15) * 2;
        ra2 = *(const float2*)(A0 + (size_t)m*lda + kq);
    }
    #pragma unroll
    for (int i = 0; i < 8; i++) {
        int s = tid + i*128;
        rb[i] = *(const float4*)(Bsrc + (size_t)(s>>5)*128 + ((s&31)<<2));
    }
    // store tile 0
    if (ROWS == 16) {
        int m = tid >> 3, kq = (tid & 7) * 4;
        *(float2*)&As[0][kq+0][2*m] = make_float2(ra.x, ra.x);
        *(float2*)&As[0][kq+1][2*m] = make_float2(ra.y, ra.y);
        *(float2*)&As[0][kq+2][2*m] = make_float2(ra.z, ra.z);
        *(float2*)&As[0][kq+3][2*m] = make_float2(ra.w, ra.w);
    } else {
        int m = tid >> 4, kq = (tid & 15) * 2;
        *(float2*)&As[0][kq+0][2*m] = make_float2(ra2.x, ra2.x);
        *(float2*)&As[0][kq+1][2*m] = make_float2(ra2.y, ra2.y);
    }
    #pragma unroll
    for (int i = 0; i < 8; i++) {
        int s = tid + i*128;
        *(float4*)&Bs[0][s>>5][(s&31)<<2] = rb[i];
    }

    #pragma unroll 1
    for (int t = 0; t < ktiles; t++) {
        __syncthreads();
        if (t + 1 < ktiles) {
            int k0 = (t+1)*BKC;
            if (ROWS == 16) {
                int m = tid >> 3, kq = (tid & 7) * 4;
                ra = *(const float4*)(A0 + (size_t)m*lda + k0 + kq);
            } else {
                int m = tid >> 4, kq = (tid & 15) * 2;
                ra2 = *(const float2*)(A0 + (size_t)m*lda + k0 + kq);
            }
            #pragma unroll
            for (int i = 0; i < 8; i++) {
                int s = tid + i*128;
                rb[i] = *(const float4*)(Bsrc + (size_t)(k0+(s>>5))*128 + ((s&31)<<2));
            }
        }
        const int b = t & 1;
        #pragma unroll
        for (int kk = 0; kk < BKC; kk++) {
            ulonglong2 bv = *(const ulonglong2*)&Bs[b][kk][l*4];
            if (RPW == 4) {
                ulonglong2 a01 = *(const ulonglong2*)&As[b][kk][8*warp];
                ulonglong2 a23 = *(const ulonglong2*)&As[b][kk][8*warp+4];
                ffma2(acc[0][0], a01.x, bv.x); ffma2(acc[0][1], a01.x, bv.y);
                ffma2(acc[1][0], a01.y, bv.x); ffma2(acc[1][1], a01.y, bv.y);
                ffma2(acc[2][0], a23.x, bv.x); ffma2(acc[2][1], a23.x, bv.y);
                ffma2(acc[RPW-1][0], a23.y, bv.x); ffma2(acc[RPW-1][1], a23.y, bv.y);
            } else {
                ulonglong2 a01 = *(const ulonglong2*)&As[b][kk][4*warp];
                ffma2(acc[0][0], a01.x, bv.x); ffma2(acc[0][1], a01.x, bv.y);
                ffma2(acc[RPW-1][0], a01.y, bv.x); ffma2(acc[RPW-1][1], a01.y, bv.y);
            }
        }
        if (t + 1 < ktiles) {
            const int nb = (t+1) & 1;
            if (ROWS == 16) {
                int m = tid >> 3, kq = (tid & 7) * 4;
                *(float2*)&As[nb][kq+0][2*m] = make_float2(ra.x, ra.x);
                *(float2*)&As[nb][kq+1][2*m] = make_float2(ra.y, ra.y);
                *(float2*)&As[nb][kq+2][2*m] = make_float2(ra.z, ra.z);
                *(float2*)&As[nb][kq+3][2*m] = make_float2(ra.w, ra.w);
            } else {
                int m = tid >> 4, kq = (tid & 15) * 2;
                *(float2*)&As[nb][kq+0][2*m] = make_float2(ra2.x, ra2.x);
                *(float2*)&As[nb][kq+1][2*m] = make_float2(ra2.y, ra2.y);
            }
            #pragma unroll
            for (int i = 0; i < 8; i++) {
                int s = tid + i*128;
                *(float4*)&Bs[nb][s>>5][(s&31)<<2] = rb[i];
            }
        }
    }
}

// ---- persistent kernel: power iteration + 500 ISTA iterations ----
__global__ void __launch_bounds__(128, 1) persist_k(const float* __restrict__ basis)
{
    __shared__ __align__(16) float As[2][BKC][40];
    __shared__ __align__(16) float Bs[2][BKC][128];
    __shared__ float red1[4], red2[4];
    __shared__ float sh_b;
    const int cta = blockIdx.x, tid = threadIdx.x;
    unsigned gen = 0;

    // ---- power iteration: 8 matvecs on dir(S^64) (g_T0), then S + Rayleigh ----
    for (int pi = 0; pi < 9; pi++) {
        const float* M = (pi < 8) ? g_T0 : g_S;
        {
            int row = cta*8 + (tid >> 4), l = tid & 15;
            const float* mr = M + (size_t)row*ED;
            float s = 0.0f;
            for (int j = l; j < ED; j += 16) s = fmaf(mr[j], g_v[j], s);
            #pragma unroll
            for (int o = 8; o; o >>= 1) s += __shfl_xor_sync(~0u, s, o, 16);
            if (l == 0) g_w[row] = s;
        }
        gen++; gsync(gen);
        if (cta == 0) {
            if (pi < 8) {
                float x[8], ss = 0.0f;
                #pragma unroll
                for (int i = 0; i < 8; i++) { x[i] = g_w[tid*8+i]; ss += x[i]*x[i]; }
                #pragma unroll
                for (int o = 16; o; o >>= 1) ss += __shfl_xor_sync(~0u, ss, o);
                if ((tid & 31) == 0) red1[tid>>5] = ss;
                __syncthreads();
                if (tid == 0) sh_b = rsqrtf(red1[0]+red1[1]+red1[2]+red1[3]);
                __syncthreads();
                float rs = sh_b;
                #pragma unroll
                for (int i = 0; i < 8; i++) g_v[tid*8+i] = x[i]*rs;
            } else {
                float d1 = 0.0f, d2 = 0.0f;
                #pragma unroll
                for (int i = 0; i < 8; i++) {
                    float vv = g_v[tid*8+i], ww = g_w[tid*8+i];
                    d1 = fmaf(vv, ww, d1); d2 = fmaf(vv, vv, d2);
                }
                #pragma unroll
                for (int o = 16; o; o >>= 1) {
                    d1 += __shfl_xor_sync(~0u, d1, o);
                    d2 += __shfl_xor_sync(~0u, d2, o);
                }
                if ((tid & 31) == 0) { red1[tid>>5] = d1; red2[tid>>5] = d2; }
                __syncthreads();
                if (tid == 0) {
                    float lam = (red1[0]+red1[1]+red1[2]+red1[3]) /
                                (red2[0]+red2[1]+red2[2]+red2[3]);
                    g_scal[0] = lam;
                    g_scal[1] = 1.0f / lam;
                    g_scal[2] = LAMB_C / lam;
                }
                __syncthreads();
            }
        }
        gen++; gsync(gen);
    }

    const float eta = g_scal[1], thr = g_scal[2];
    const int warp = tid >> 5, l = tid & 31;

    for (int it = 0; it < NITER; it++) {
        // Phase A: a(16 rows/CTA) = shrink(a + eta * BT * r, thr), K=1024
        {
            unsigned long long acc[4][2] = {};
            tile_mm2<16>(g_BT + (size_t)(cta*16)*ED, ED, g_r, 32, As, Bs, acc, tid);
            #pragma unroll
            for (int i = 0; i < 4; i++) {
                int row = cta*16 + warp*4 + i;
                float4* ap = (float4*)&g_a[(size_t)row*BA + l*4];
                float4 o = *ap;
                float2 p0 = upk(acc[i][0]), p1 = upk(acc[i][1]);
                o.x = sshrinkf(o.x + eta*p0.x, thr);
                o.y = sshrinkf(o.y + eta*p0.y, thr);
                o.z = sshrinkf(o.z + eta*p1.x, thr);
                o.w = sshrinkf(o.w + eta*p1.y, thr);
                *ap = o;
            }
        }
        gen++; gsync(gen);
        // Phase B (fused C): r(8 rows/CTA) = It - basis * a, K=2048 full
        {
            unsigned long long acc[2][2] = {};
            tile_mm2<8>(basis + (size_t)(cta*8)*BD, BD, g_a, 64, As, Bs, acc, tid);
            #pragma unroll
            for (int i = 0; i < 2; i++) {
                int row = cta*8 + warp*2 + i;
                float4 iv = *(const float4*)&g_It[(size_t)row*BA + l*4];
                float2 p0 = upk(acc[i][0]), p1 = upk(acc[i][1]);
                *(float4*)&g_r[(size_t)row*BA + l*4] =
                    make_float4(iv.x - p0.x, iv.y - p0.y, iv.z - p1.x, iv.w - p1.y);
            }
        }
        gen++; gsync(gen);
    }
}

// ---------------- NT GEMM (prologue/epilogue nodes) ----------------
template<int EPI>
__global__ void __launch_bounds__(128, 2) gemm_nt_k(
    const float* __restrict__ A, const float* __restrict__ Bm,
    float* __restrict__ C, const float* __restrict__ Aux,
    int Nh, int Kh)
{
    __shared__ float As[2][64][18];
    __shared__ float Bs[2][64][68];
    const int tid = threadIdx.x;
    const int tx = tid & 15, ty = tid >> 4;
    const float* Ab = A + (size_t)blockIdx.y * 16 * Kh;
    const float* Bb = Bm + (size_t)blockIdx.x * 64 * Kh;
    const int ar0 = tid >> 4, ar1 = (tid + 128) >> 4, ak = (tid & 15) * 4;

    float4 ra0, ra1, rb[8];
    float acc[2][4] = {{0,0,0,0},{0,0,0,0}};

    ra0 = *(const float4*)(Ab + (size_t)ar0*Kh + ak);
    ra1 = *(const float4*)(Ab + (size_t)ar1*Kh + ak);
    #pragma unroll
    for (int i = 0; i < 8; i++) {
        int q = tid + i*128;
        rb[i] = *(const float4*)(Bb + (size_t)(q>>4)*Kh + (q&15)*4);
    }
    As[0][ak+0][ar0]=ra0.x; As[0][ak+1][ar0]=ra0.y; As[0][ak+2][ar0]=ra0.z; As[0][ak+3][ar0]=ra0.w;
    As[0][ak+0][ar1]=ra1.x; As[0][ak+1][ar1]=ra1.y; As[0][ak+2][ar1]=ra1.z; As[0][ak+3][ar1]=ra1.w;
    #pragma unroll
    for (int i = 0; i < 8; i++) {
        int q = tid + i*128; int n = q>>4; int kq = (q&15)*4;
        Bs[0][kq+0][n]=rb[i].x; Bs[0][kq+1][n]=rb[i].y; Bs[0][kq+2][n]=rb[i].z; Bs[0][kq+3][n]=rb[i].w;
    }

    const int T = Kh >> 6;
    for (int t = 0; t < T; t++) {
        __syncthreads();
        if (t + 1 < T) {
            int k0 = (t+1) * 64;
            ra0 = *(const float4*)(Ab + (size_t)ar0*Kh + k0 + ak);
            ra1 = *(const float4*)(Ab + (size_t)ar1*Kh + k0 + ak);
            #pragma unroll
            for (int i = 0; i < 8; i++) {
                int q = tid + i*128;
                rb[i] = *(const float4*)(Bb + (size_t)(q>>4)*Kh + k0 + (q&15)*4);
            }
        }
        const int buf = t & 1;
        #pragma unroll
        for (int kk = 0; kk < 64; kk++) {
            float2 av = *(const float2*)&As[buf][kk][ty*2];
            float4 bv = *(const float4*)&Bs[buf][kk][tx*4];
            acc[0][0]=fmaf(av.x,bv.x,acc[0][0]); acc[0][1]=fmaf(av.x,bv.y,acc[0][1]);
            acc[0][2]=fmaf(av.x,bv.z,acc[0][2]); acc[0][3]=fmaf(av.x,bv.w,acc[0][3]);
            acc[1][0]=fmaf(av.y,bv.x,acc[1][0]); acc[1][1]=fmaf(av.y,bv.y,acc[1][1]);
            acc[1][2]=fmaf(av.y,bv.z,acc[1][2]); acc[1][3]=fmaf(av.y,bv.w,acc[1][3]);
        }
        if (t + 1 < T) {
            const int nb = (t+1) & 1;
            As[nb][ak+0][ar0]=ra0.x; As[nb][ak+1][ar0]=ra0.y; As[nb][ak+2][ar0]=ra0.z; As[nb][ak+3][ar0]=ra0.w;
            As[nb][ak+0][ar1]=ra1.x; As[nb][ak+1][ar1]=ra1.y; As[nb][ak+2][ar1]=ra1.z; As[nb][ak+3][ar1]=ra1.w;
            #pragma unroll
            for (int i = 0; i < 8; i++) {
                int q = tid + i*128; int n = q>>4; int kq = (q&15)*4;
                Bs[nb][kq+0][n]=rb[i].x; Bs[nb][kq+1][n]=rb[i].y; Bs[nb][kq+2][n]=rb[i].z; Bs[nb][kq+3][n]=rb[i].w;
            }
        }
    }

    const int gm = blockIdx.y*16 + ty*2;
    const int gn = blockIdx.x*64 + tx*4;
    if (EPI == 0) {
        #pragma unroll
        for (int mi = 0; mi < 2; mi++)
            *(float4*)(C + (size_t)(gm+mi)*Nh + gn) =
                make_float4(acc[mi][0],acc[mi][1],acc[mi][2],acc[mi][3]);
    } else if (EPI == 3) {
        const float s2 = g_scal[3] * g_scal[3];
        #pragma unroll
        for (int mi = 0; mi < 2; mi++)
            *(float4*)(C + (size_t)(gm+mi)*Nh + gn) =
                make_float4(acc[mi][0]*s2,acc[mi][1]*s2,acc[mi][2]*s2,acc[mi][3]*s2);
    } else {
        #pragma unroll
        for (int mi = 0; mi < 2; mi++)
            #pragma unroll
            for (int ni = 0; ni < 4; ni++) {
                int col = gn + ni;
                C[(size_t)(gm+mi)*Nh + col] = Aux[(size_t)(gm+mi)*Nh + col] +
                    (H_C/(float)BA) * acc[mi][ni] / (g_hes[col] + LOWACT);
            }
    }
}

// ---------------- helpers ----------------
__global__ void transpose_k(const float* __restrict__ in, float* __restrict__ out,
                            float* __restrict__ out2, int rows, int cols)
{
    __shared__ float sm[32][33];
    int bx = blockIdx.x*32, by = blockIdx.y*32;
    int tx = threadIdx.x, ty = threadIdx.y;
    #pragma unroll
    for (int j = 0; j < 32; j += 8)
        sm[ty+j][tx] = in[(size_t)(by+ty+j)*cols + bx+tx];
    __syncthreads();
    #pragma unroll
    for (int j = 0; j < 32; j += 8) {
        float v = sm[tx][ty+j];
        size_t o = (size_t)(bx+ty+j)*rows + by+tx;
        out[o] = v;
        if (out2) out2[o] = v;
    }
}

__global__ void init_k(float* a) {
    int idx = blockIdx.x*blockDim.x + threadIdx.x;
    if (idx < BD*BA) a[idx] = 0.0f;
    if (idx < ED) g_v[idx] = 1.0f;
    if (idx == 0) { g_scal[4] = 0.0f; g_cnt = 0; g_gen = 0; }
}

__global__ void copyN_k(const float* __restrict__ in, float* __restrict__ out, int n) {
    int i = blockIdx.x*256 + threadIdx.x;
    if (i < n) out[i] = in[i];
}

__global__ void diagmax_k(const float* __restrict__ T) {
    __shared__ float red[32];
    int tid = threadIdx.x;
    float m = fabsf(T[(size_t)tid*ED + tid]);
    #pragma unroll
    for (int o = 16; o; o >>= 1) m = fmaxf(m, __shfl_xor_sync(~0u, m, o));
    if ((tid&31)==0) red[tid>>5] = m;
    __syncthreads();
    if (tid < 32) {
        float mm = red[tid];
        #pragma unroll
        for (int o = 16; o; o >>= 1) mm = fmaxf(mm, __shfl_xor_sync(~0u, mm, o));
        if (tid == 0) g_scal[3] = 1.0f / mm;
    }
}

__global__ void rowstats_k(const float* __restrict__ a, const float* __restrict__ hd,
                           const float* __restrict__ l1h,
                           float* __restrict__ out_hes, float* __restrict__ out_l1)
{
    __shared__ float s1s[4], s2s[4];
    int m = blockIdx.x, tid = threadIdx.x;
    float av = a[(size_t)m*BA + tid];
    float s1 = fabsf(av), s2 = av*av;
    #pragma unroll
    for (int o = 16; o; o >>= 1) {
        s1 += __shfl_xor_sync(~0u, s1, o);
        s2 += __shfl_xor_sync(~0u, s2, o);
    }
    if ((tid&31)==0) { s1s[tid>>5]=s1; s2s[tid>>5]=s2; }
    __syncthreads();
    if (tid == 0) {
        float t1 = s1s[0]+s1s[1]+s1s[2]+s1s[3];
        float t2 = s2s[0]+s2s[1]+s2s[2]+s2s[3];
        float he = hd[m]*RMC + t2*(1.0f/(BA*100.0f));
        out_l1[m] = l1h[m]*RMC + t1*(1.0f/(BA*100.0f));
        out_hes[m] = he;
        g_hes[m] = he;
        g_nsq[m] = 0.0f;
    }
}

__global__ void colnorm1_k(const float* __restrict__ NB) {
    int col = blockIdx.x*256 + threadIdx.x;
    int r0 = blockIdx.y*128;
    float s = 0.0f;
    for (int r = r0; r < r0+128; r++) {
        float v = NB[(size_t)r*BD + col];
        s = fmaf(v, v, s);
    }
    atomicAdd(&g_nsq[col], s);
}

__global__ void colnorm2_k(const float* __restrict__ NB, float* __restrict__ out) {
    int i = blockIdx.x*blockDim.x + threadIdx.x;
    if (i < ED*BD) out[i] = NB[i] * rsqrtf(g_nsq[i & (BD-1)]);
}

__global__ void copy_a_k(const float* __restrict__ a, float* __restrict__ out) {
    int i = blockIdx.x*blockDim.x + threadIdx.x;
    if (i < BD*BA) out[i] = a[i];
}

__global__ void sumI2_k(const float* __restrict__ I) {
    __shared__ float red[8];
    int tid = threadIdx.x;
    float s = 0.0f;
    for (int i = blockIdx.x*blockDim.x + tid; i < ED*BA; i += gridDim.x*blockDim.x) {
        float v = I[i];
        s = fmaf(v, v, s);
    }
    #pragma unroll
    for (int o = 16; o; o >>= 1) s += __shfl_xor_sync(~0u, s, o);
    if ((tid&31)==0) red[tid>>5] = s;
    __syncthreads();
    if (tid == 0) {
        float t = 0.0f;
        #pragma unroll
        for (int i = 0; i < 8; i++) t += red[i];
        atomicAdd(&g_scal[4], t);
    }
}

__global__ void scalarfin_k(const float* __restrict__ se, const float* __restrict__ ne,
                            float* __restrict__ out_snr)
{
    float ns = se[0]*RMC + g_scal[4]*0.01f;
    out_snr[0] = ns / (ne[0]*RMC);
}

extern "C" void kernel_launch(void* const* d_in, const int* in_sizes, int n_in,
                              void* d_out, int out_size)
{
    const float* I     = (const float*)d_in[0];
    const float* basis = (const float*)d_in[1];
    const float* hd    = (const float*)d_in[2];
    const float* l1h   = (const float*)d_in[3];
    const float* se    = (const float*)d_in[4];
    const float* ne    = (const float*)d_in[5];
    float* out = (float*)d_out;

    float *BT,*It,*a,*r,*S,*T0,*T1,*NB;
    cudaGetSymbolAddress((void**)&BT, g_BT);
    cudaGetSymbolAddress((void**)&It, g_It);
    cudaGetSymbolAddress((void**)&a,  g_a);
    cudaGetSymbolAddress((void**)&r,  g_r);
    cudaGetSymbolAddress((void**)&S,  g_S);
    cudaGetSymbolAddress((void**)&T0, g_T0);
    cudaGetSymbolAddress((void**)&T1, g_T1);
    cudaGetSymbolAddress((void**)&NB, g_NB);

    transpose_k<<<dim3(BD/32, ED/32), dim3(32,8)>>>(basis, BT, nullptr, ED, BD);
    transpose_k<<<dim3(ED/32, BA/32), dim3(32,8)>>>(I, It, r, BA, ED);
    init_k<<<(BD*BA+255)/256, 256>>>(a);

    // S = B B^T, then 6 renormalized squarings -> g_T0 = dir(S^64)
    gemm_nt_k<0><<<dim3(ED/64, ED/16), 128>>>(basis, basis, S, nullptr, ED, BD);
    copyN_k<<<(ED*ED+255)/256, 256>>>(S, T0, ED*ED);
    float* sq[2] = {T0, T1};
    for (int i = 0; i < 6; i++) {
        diagmax_k<<<1, 1024>>>(sq[0]);
        gemm_nt_k<3><<<dim3(ED/64, ED/16), 128>>>(sq[0], sq[0], sq[1], nullptr, ED, ED);
        float* t = sq[0]; sq[0] = sq[1]; sq[1] = t;
    }

    persist_k<<<GRID, 128>>>(basis);

    rowstats_k<<<BD, 128>>>(a, hd, l1h, out + O_HES, out + O_L1);
    gemm_nt_k<4><<<dim3(BD/64, ED/16), 128>>>(r, a, NB, basis, BD, BA);
    colnorm1_k<<<dim3(BD/256, ED/128), 256>>>(NB);
    colnorm2_k<<<(ED*BD+255)/256, 256>>>(NB, out + O_BASIS);
    copy_a_k<<<(BD*BA+255)/256, 256>>>(a, out + O_A);
    sumI2_k<<<256, 256>>>(I);
    scalarfin_k<<<1, 1>>>(se, ne, out + O_SNR);
}

// round 6
// speedup vs baseline: 1.4202x; 1.4202x over previous
#include <cuda_runtime.h>
#include <cstddef>

#define ED 1024
#define BD 2048
#define BA 128
#define NITER 500
#define LAMB_C 0.3f
#define H_C 0.005f
#define RMC 0.99f
#define LOWACT 0.001f
#define GRID 128

#define O_A     ((size_t)0)
#define O_BASIS ((size_t)(BD*BA))
#define O_HES   (O_BASIS + (size_t)ED*BD)
#define O_L1    (O_HES + BD)
#define O_SNR   (O_L1 + BD)

__device__ float g_BT[(size_t)BD*ED];
__device__ float g_It[(size_t)ED*BA];
__device__ float g_a [(size_t)BD*BA];
__device__ float g_a2[(size_t)BD*BA];
__device__ float g_c [(size_t)BD*BA];
__device__ float g_G [(size_t)BD*BD];
__device__ float g_r [(size_t)ED*BA];
__device__ float g_S [(size_t)ED*ED];
__device__ float g_T0[(size_t)ED*ED];
__device__ float g_T1[(size_t)ED*ED];
__device__ float g_NB[(size_t)ED*BD];
__device__ float g_hes[BD];
__device__ float g_nsq[BD];
__device__ float g_v[ED];
__device__ float g_w[ED];
__device__ float g_scal[8];             // 0:lam 1:eta 2:thr 3:scale 4:sumI2
__device__ unsigned g_cnt;
__device__ volatile unsigned g_gen;

__device__ __forceinline__ float sshrinkf(float v, float thr) {
    float t = fabsf(v) - thr;
    return t > 0.0f ? copysignf(t, v) : 0.0f;
}

// packed fp32 FMA: d = a*b + d, rounding identical to scalar fmaf (verified R5)
__device__ __forceinline__ void ffma2(unsigned long long &d, unsigned long long a,
                                      unsigned long long b) {
    asm("fma.rn.f32x2 %0, %1, %2, %0;" : "+l"(d) : "l"(a), "l"(b));
}
__device__ __forceinline__ float2 upk(unsigned long long v) {
    float2 f;
    asm("mov.b64 {%0, %1}, %2;" : "=f"(f.x), "=f"(f.y) : "l"(v));
    return f;
}

// ---- software grid barrier ----
__device__ __forceinline__ void gsync(unsigned gen) {
    __syncthreads();
    if (threadIdx.x == 0) {
        __threadfence();
        unsigned t = atomicAdd(&g_cnt, 1u);
        if (t == GRID - 1) {
            g_cnt = 0;
            __threadfence();
            g_gen = gen;
        } else {
            while (g_gen < gen) { }
            __threadfence();
        }
    }
    __syncthreads();
}

// ---- persistent kernel: power iteration + 500 Gram-ISTA iterations + residual ----
__global__ void __launch_bounds__(256, 1) persist_k(const float* __restrict__ basis)
{
    __shared__ __align__(16) float As[2][32][132];   // a-tile (k x 128 cols), padded
    __shared__ __align__(16) float Gs[2][32][34];    // G-tile duplicated {g,g}, padded
    __shared__ float Bsr[8][32];
    __shared__ float red1[8], red2[8];
    __shared__ float sh_b;
    const int cta = blockIdx.x, tid = threadIdx.x;
    const int w = tid >> 5, l = tid & 31;
    unsigned gen = 0;

    // ---- power iteration: 8 matvecs on dir(S^64) (g_T0), then S + Rayleigh ----
    for (int pi = 0; pi < 9; pi++) {
        const float* M = (pi < 8) ? g_T0 : g_S;
        {
            int row = cta*8 + w;
            const float* mr = M + (size_t)row*ED;
            float s = 0.f;
            for (int j = l; j < ED; j += 32) s = fmaf(mr[j], g_v[j], s);
            #pragma unroll
            for (int o = 16; o; o >>= 1) s += __shfl_xor_sync(~0u, s, o);
            if (l == 0) g_w[row] = s;
        }
        gen++; gsync(gen);
        if (cta == 0) {
            if (pi < 8) {
                float x[4], ss = 0.f;
                #pragma unroll
                for (int i = 0; i < 4; i++) { x[i] = g_w[tid*4+i]; ss = fmaf(x[i], x[i], ss); }
                #pragma unroll
                for (int o = 16; o; o >>= 1) ss += __shfl_xor_sync(~0u, ss, o);
                if (l == 0) red1[w] = ss;
                __syncthreads();
                if (tid == 0) {
                    float t = 0.f;
                    #pragma unroll
                    for (int i = 0; i < 8; i++) t += red1[i];
                    sh_b = rsqrtf(t);
                }
                __syncthreads();
                float rs = sh_b;
                #pragma unroll
                for (int i = 0; i < 4; i++) g_v[tid*4+i] = x[i]*rs;
            } else {
                float d1 = 0.f, d2 = 0.f;
                #pragma unroll
                for (int i = 0; i < 4; i++) {
                    float vv = g_v[tid*4+i], ww = g_w[tid*4+i];
                    d1 = fmaf(vv, ww, d1); d2 = fmaf(vv, vv, d2);
                }
                #pragma unroll
                for (int o = 16; o; o >>= 1) {
                    d1 += __shfl_xor_sync(~0u, d1, o);
                    d2 += __shfl_xor_sync(~0u, d2, o);
                }
                if (l == 0) { red1[w] = d1; red2[w] = d2; }
                __syncthreads();
                if (tid == 0) {
                    float a = 0.f, b = 0.f;
                    #pragma unroll
                    for (int i = 0; i < 8; i++) { a += red1[i]; b += red2[i]; }
                    float lam = a / b;
                    g_scal[0] = lam;
                    g_scal[1] = 1.0f / lam;
                    g_scal[2] = LAMB_C / lam;
                }
                __syncthreads();
            }
        }
        gen++; gsync(gen);
    }

    const float eta = g_scal[1], thr = g_scal[2];
    // micro-tile mapping: warp w -> cols [16w,16w+16); lane: cg = l&3, rp = l>>2
    const int cg = l & 3, rp = l >> 2;
    const int col0 = w*16 + cg*4;
    const int row0 = cta*16;
    // loader indices
    const int lar = tid >> 3, lac = tid & 7;       // a-tile: k-row 0..31, col-group 0..7
    const int lgr = tid >> 4, lgk = (tid & 15)*2;  // G-tile: row 0..15, k-offset 0..30
    const float* Grow = g_G + (size_t)(row0 + lgr)*BD + lgk;

    // ---- 500 Gram-ISTA iterations: a_nxt = shrink(a_cur + eta*(c - G a_cur)) ----
    for (int it = 0; it < NITER; it++) {
        const float* acur = (it & 1) ? g_a2 : g_a;
        float*       anxt = (it & 1) ? g_a  : g_a2;

        unsigned long long a00 = 0, a01 = 0, a10 = 0, a11 = 0;
        float4 rA[4]; float2 rG;

        // prefetch tile 0
        #pragma unroll
        for (int i = 0; i < 4; i++)
            rA[i] = *(const float4*)&acur[(size_t)lar*BA + 4*(lac + 8*i)];
        rG = *(const float2*)&Grow[0];
        #pragma unroll
        for (int i = 0; i < 4; i++)
            *(float4*)&As[0][lar][4*(lac + 8*i)] = rA[i];
        *(float2*)&Gs[0][lgk  ][2*lgr] = make_float2(rG.x, rG.x);
        *(float2*)&Gs[0][lgk+1][2*lgr] = make_float2(rG.y, rG.y);

        #pragma unroll 1
        for (int t = 0; t < 64; t++) {
            __syncthreads();
            if (t < 63) {
                int k0 = (t+1)*32;
                #pragma unroll
                for (int i = 0; i < 4; i++)
                    rA[i] = *(const float4*)&acur[(size_t)(k0 + lar)*BA + 4*(lac + 8*i)];
                rG = *(const float2*)&Grow[k0];
            }
            const int b = t & 1;
            #pragma unroll
            for (int kk = 0; kk < 32; kk++) {
                ulonglong2 av = *(const ulonglong2*)&As[b][kk][col0];
                unsigned long long gv0 = *(const unsigned long long*)&Gs[b][kk][2*rp];
                unsigned long long gv1 = *(const unsigned long long*)&Gs[b][kk][2*rp + 16];
                ffma2(a00, gv0, av.x); ffma2(a01, gv0, av.y);
                ffma2(a10, gv1, av.x); ffma2(a11, gv1, av.y);
            }
            if (t < 63) {
                const int nb = (t+1) & 1;
                #pragma unroll
                for (int i = 0; i < 4; i++)
                    *(float4*)&As[nb][lar][4*(lac + 8*i)] = rA[i];
                *(float2*)&Gs[nb][lgk  ][2*lgr] = make_float2(rG.x, rG.x);
                *(float2*)&Gs[nb][lgk+1][2*lgr] = make_float2(rG.y, rG.y);
            }
        }
        // epilogue: 2 rows x 4 cols per thread
        {
            int r0 = row0 + rp, r1 = row0 + rp + 8;
            float2 p00 = upk(a00), p01 = upk(a01), p10 = upk(a10), p11 = upk(a11);
            float4 ao = *(const float4*)&acur[(size_t)r0*BA + col0];
            float4 cv = *(const float4*)&g_c[(size_t)r0*BA + col0];
            float4 o;
            o.x = sshrinkf(ao.x + eta*(cv.x - p00.x), thr);
            o.y = sshrinkf(ao.y + eta*(cv.y - p00.y), thr);
            o.z = sshrinkf(ao.z + eta*(cv.z - p01.x), thr);
            o.w = sshrinkf(ao.w + eta*(cv.w - p01.y), thr);
            *(float4*)&anxt[(size_t)r0*BA + col0] = o;
            ao = *(const float4*)&acur[(size_t)r1*BA + col0];
            cv = *(const float4*)&g_c[(size_t)r1*BA + col0];
            o.x = sshrinkf(ao.x + eta*(cv.x - p10.x), thr);
            o.y = sshrinkf(ao.y + eta*(cv.y - p10.y), thr);
            o.z = sshrinkf(ao.z + eta*(cv.z - p11.x), thr);
            o.w = sshrinkf(ao.w + eta*(cv.w - p11.y), thr);
            *(float4*)&anxt[(size_t)r1*BA + col0] = o;
        }
        gen++; gsync(gen);
    }

    // ---- final residual: r(8 rows/CTA) = It - basis * a, K=2048 (one-shot) ----
    {
        const int rrow = cta*8 + w;     // warp w -> one row
        float racc0 = 0.f, racc1 = 0.f, racc2 = 0.f, racc3 = 0.f;
        for (int t = 0; t < 64; t++) {
            int k0 = t*32;
            float4 rAv[4];
            #pragma unroll
            for (int i = 0; i < 4; i++)
                rAv[i] = *(const float4*)&g_a[(size_t)(k0 + lar)*BA + 4*(lac + 8*i)];
            float rB = basis[(size_t)rrow*BD + k0 + l];
            __syncthreads();
            #pragma unroll
            for (int i = 0; i < 4; i++)
                *(float4*)&As[0][lar][4*(lac + 8*i)] = rAv[i];
            Bsr[w][l] = rB;
            __syncthreads();
            #pragma unroll 4
            for (int kk = 0; kk < 32; kk++) {
                float bb = Bsr[w][kk];
                float4 avv = *(const float4*)&As[0][kk][l*4];
                racc0 = fmaf(bb, avv.x, racc0);
                racc1 = fmaf(bb, avv.y, racc1);
                racc2 = fmaf(bb, avv.z, racc2);
                racc3 = fmaf(bb, avv.w, racc3);
            }
        }
        float4 iv = *(const float4*)&g_It[(size_t)rrow*BA + l*4];
        *(float4*)&g_r[(size_t)rrow*BA + l*4] =
            make_float4(iv.x - racc0, iv.y - racc1, iv.z - racc2, iv.w - racc3);
    }
}

// ---------------- NT GEMM (prologue/epilogue nodes) ----------------
// EPI 0: store   EPI 3: store*scale^2   EPI 4: NB = Aux + (H/BA)*acc/(hes+eps)
template<int EPI>
__global__ void __launch_bounds__(128, 2) gemm_nt_k(
    const float* __restrict__ A, const float* __restrict__ Bm,
    float* __restrict__ C, const float* __restrict__ Aux,
    int Nh, int Kh)
{
    __shared__ float As[2][64][18];
    __shared__ float Bs[2][64][68];
    const int tid = threadIdx.x;
    const int tx = tid & 15, ty = tid >> 4;
    const float* Ab = A + (size_t)blockIdx.y * 16 * Kh;
    const float* Bb = Bm + (size_t)blockIdx.x * 64 * Kh;
    const int ar0 = tid >> 4, ar1 = (tid + 128) >> 4, ak = (tid & 15) * 4;

    float4 ra0, ra1, rb[8];
    float acc[2][4] = {{0,0,0,0},{0,0,0,0}};

    ra0 = *(const float4*)(Ab + (size_t)ar0*Kh + ak);
    ra1 = *(const float4*)(Ab + (size_t)ar1*Kh + ak);
    #pragma unroll
    for (int i = 0; i < 8; i++) {
        int q = tid + i*128;
        rb[i] = *(const float4*)(Bb + (size_t)(q>>4)*Kh + (q&15)*4);
    }
    As[0][ak+0][ar0]=ra0.x; As[0][ak+1][ar0]=ra0.y; As[0][ak+2][ar0]=ra0.z; As[0][ak+3][ar0]=ra0.w;
    As[0][ak+0][ar1]=ra1.x; As[0][ak+1][ar1]=ra1.y; As[0][ak+2][ar1]=ra1.z; As[0][ak+3][ar1]=ra1.w;
    #pragma unroll
    for (int i = 0; i < 8; i++) {
        int q = tid + i*128; int n = q>>4; int kq = (q&15)*4;
        Bs[0][kq+0][n]=rb[i].x; Bs[0][kq+1][n]=rb[i].y; Bs[0][kq+2][n]=rb[i].z; Bs[0][kq+3][n]=rb[i].w;
    }

    const int T = Kh >> 6;
    for (int t = 0; t < T; t++) {
        __syncthreads();
        if (t + 1 < T) {
            int k0 = (t+1) * 64;
            ra0 = *(const float4*)(Ab + (size_t)ar0*Kh + k0 + ak);
            ra1 = *(const float4*)(Ab + (size_t)ar1*Kh + k0 + ak);
            #pragma unroll
            for (int i = 0; i < 8; i++) {
                int q = tid + i*128;
                rb[i] = *(const float4*)(Bb + (size_t)(q>>4)*Kh + k0 + (q&15)*4);
            }
        }
        const int buf = t & 1;
        #pragma unroll
        for (int kk = 0; kk < 64; kk++) {
            float2 av = *(const float2*)&As[buf][kk][ty*2];
            float4 bv = *(const float4*)&Bs[buf][kk][tx*4];
            acc[0][0]=fmaf(av.x,bv.x,acc[0][0]); acc[0][1]=fmaf(av.x,bv.y,acc[0][1]);
            acc[0][2]=fmaf(av.x,bv.z,acc[0][2]); acc[0][3]=fmaf(av.x,bv.w,acc[0][3]);
            acc[1][0]=fmaf(av.y,bv.x,acc[1][0]); acc[1][1]=fmaf(av.y,bv.y,acc[1][1]);
            acc[1][2]=fmaf(av.y,bv.z,acc[1][2]); acc[1][3]=fmaf(av.y,bv.w,acc[1][3]);
        }
        if (t + 1 < T) {
            const int nb = (t+1) & 1;
            As[nb][ak+0][ar0]=ra0.x; As[nb][ak+1][ar0]=ra0.y; As[nb][ak+2][ar0]=ra0.z; As[nb][ak+3][ar0]=ra0.w;
            As[nb][ak+0][ar1]=ra1.x; As[nb][ak+1][ar1]=ra1.y; As[nb][ak+2][ar1]=ra1.z; As[nb][ak+3][ar1]=ra1.w;
            #pragma unroll
            for (int i = 0; i < 8; i++) {
                int q = tid + i*128; int n = q>>4; int kq = (q&15)*4;
                Bs[nb][kq+0][n]=rb[i].x; Bs[nb][kq+1][n]=rb[i].y; Bs[nb][kq+2][n]=rb[i].z; Bs[nb][kq+3][n]=rb[i].w;
            }
        }
    }

    const int gm = blockIdx.y*16 + ty*2;
    const int gn = blockIdx.x*64 + tx*4;
    if (EPI == 0) {
        #pragma unroll
        for (int mi = 0; mi < 2; mi++)
            *(float4*)(C + (size_t)(gm+mi)*Nh + gn) =
                make_float4(acc[mi][0],acc[mi][1],acc[mi][2],acc[mi][3]);
    } else if (EPI == 3) {
        const float s2 = g_scal[3] * g_scal[3];
        #pragma unroll
        for (int mi = 0; mi < 2; mi++)
            *(float4*)(C + (size_t)(gm+mi)*Nh + gn) =
                make_float4(acc[mi][0]*s2,acc[mi][1]*s2,acc[mi][2]*s2,acc[mi][3]*s2);
    } else {
        #pragma unroll
        for (int mi = 0; mi < 2; mi++)
            #pragma unroll
            for (int ni = 0; ni < 4; ni++) {
                int col = gn + ni;
                C[(size_t)(gm+mi)*Nh + col] = Aux[(size_t)(gm+mi)*Nh + col] +
                    (H_C/(float)BA) * acc[mi][ni] / (g_hes[col] + LOWACT);
            }
    }
}

// ---------------- helpers ----------------
__global__ void transpose_k(const float* __restrict__ in, float* __restrict__ out,
                            int rows, int cols)
{
    __shared__ float sm[32][33];
    int bx = blockIdx.x*32, by = blockIdx.y*32;
    int tx = threadIdx.x, ty = threadIdx.y;
    #pragma unroll
    for (int j = 0; j < 32; j += 8)
        sm[ty+j][tx] = in[(size_t)(by+ty+j)*cols + bx+tx];
    __syncthreads();
    #pragma unroll
    for (int j = 0; j < 32; j += 8)
        out[(size_t)(bx+ty+j)*rows + by+tx] = sm[tx][ty+j];
}

__global__ void init_k(float* a) {
    int idx = blockIdx.x*blockDim.x + threadIdx.x;
    if (idx < BD*BA) a[idx] = 0.0f;
    if (idx < ED) g_v[idx] = 1.0f;
    if (idx == 0) { g_scal[4] = 0.0f; g_cnt = 0; g_gen = 0; }
}

__global__ void copyN_k(const float* __restrict__ in, float* __restrict__ out, int n) {
    int i = blockIdx.x*256 + threadIdx.x;
    if (i < n) out[i] = in[i];
}

__global__ void diagmax_k(const float* __restrict__ T) {
    __shared__ float red[32];
    int tid = threadIdx.x;
    float m = fabsf(T[(size_t)tid*ED + tid]);
    #pragma unroll
    for (int o = 16; o; o >>= 1) m = fmaxf(m, __shfl_xor_sync(~0u, m, o));
    if ((tid&31)==0) red[tid>>5] = m;
    __syncthreads();
    if (tid < 32) {
        float mm = red[tid];
        #pragma unroll
        for (int o = 16; o; o >>= 1) mm = fmaxf(mm, __shfl_xor_sync(~0u, mm, o));
        if (tid == 0) g_scal[3] = 1.0f / mm;
    }
}

__global__ void rowstats_k(const float* __restrict__ a, const float* __restrict__ hd,
                           const float* __restrict__ l1h,
                           float* __restrict__ out_hes, float* __restrict__ out_l1)
{
    __shared__ float s1s[4], s2s[4];
    int m = blockIdx.x, tid = threadIdx.x;
    float av = a[(size_t)m*BA + tid];
    float s1 = fabsf(av), s2 = av*av;
    #pragma unroll
    for (int o = 16; o; o >>= 1) {
        s1 += __shfl_xor_sync(~0u, s1, o);
        s2 += __shfl_xor_sync(~0u, s2, o);
    }
    if ((tid&31)==0) { s1s[tid>>5]=s1; s2s[tid>>5]=s2; }
    __syncthreads();
    if (tid == 0) {
        float t1 = s1s[0]+s1s[1]+s1s[2]+s1s[3];
        float t2 = s2s[0]+s2s[1]+s2s[2]+s2s[3];
        float he = hd[m]*RMC + t2*(1.0f/(BA*100.0f));
        out_l1[m] = l1h[m]*RMC + t1*(1.0f/(BA*100.0f));
        out_hes[m] = he;
        g_hes[m] = he;
        g_nsq[m] = 0.0f;
    }
}

__global__ void colnorm1_k(const float* __restrict__ NB) {
    int col = blockIdx.x*256 + threadIdx.x;
    int r0 = blockIdx.y*128;
    float s = 0.0f;
    for (int r = r0; r < r0+128; r++) {
        float v = NB[(size_t)r*BD + col];
        s = fmaf(v, v, s);
    }
    atomicAdd(&g_nsq[col], s);
}

__global__ void colnorm2_k(const float* __restrict__ NB, float* __restrict__ out) {
    int i = blockIdx.x*blockDim.x + threadIdx.x;
    if (i < ED*BD) out[i] = NB[i] * rsqrtf(g_nsq[i & (BD-1)]);
}

__global__ void copy_a_k(const float* __restrict__ a, float* __restrict__ out) {
    int i = blockIdx.x*blockDim.x + threadIdx.x;
    if (i < BD*BA) out[i] = a[i];
}

__global__ void sumI2_k(const float* __restrict__ I) {
    __shared__ float red[8];
    int tid = threadIdx.x;
    float s = 0.0f;
    for (int i = blockIdx.x*blockDim.x + tid; i < ED*BA; i += gridDim.x*blockDim.x) {
        float v = I[i];
        s = fmaf(v, v, s);
    }
    #pragma unroll
    for (int o = 16; o; o >>= 1) s += __shfl_xor_sync(~0u, s, o);
    if ((tid&31)==0) red[tid>>5] = s;
    __syncthreads();
    if (tid == 0) {
        float t = 0.0f;
        #pragma unroll
        for (int i = 0; i < 8; i++) t += red[i];
        atomicAdd(&g_scal[4], t);
    }
}

__global__ void scalarfin_k(const float* __restrict__ se, const float* __restrict__ ne,
                            float* __restrict__ out_snr)
{
    float ns = se[0]*RMC + g_scal[4]*0.01f;
    out_snr[0] = ns / (ne[0]*RMC);
}

extern "C" void kernel_launch(void* const* d_in, const int* in_sizes, int n_in,
                              void* d_out, int out_size)
{
    const float* I     = (const float*)d_in[0];
    const float* basis = (const float*)d_in[1];
    const float* hd    = (const float*)d_in[2];
    const float* l1h   = (const float*)d_in[3];
    const float* se    = (const float*)d_in[4];
    const float* ne    = (const float*)d_in[5];
    float* out = (float*)d_out;

    float *BT,*It,*a,*r,*S,*T0,*T1,*NB,*G,*c;
    cudaGetSymbolAddress((void**)&BT, g_BT);
    cudaGetSymbolAddress((void**)&It, g_It);
    cudaGetSymbolAddress((void**)&a,  g_a);
    cudaGetSymbolAddress((void**)&r,  g_r);
    cudaGetSymbolAddress((void**)&S,  g_S);
    cudaGetSymbolAddress((void**)&T0, g_T0);
    cudaGetSymbolAddress((void**)&T1, g_T1);
    cudaGetSymbolAddress((void**)&NB, g_NB);
    cudaGetSymbolAddress((void**)&G,  g_G);
    cudaGetSymbolAddress((void**)&c,  g_c);

    transpose_k<<<dim3(BD/32, ED/32), dim3(32,8)>>>(basis, BT, ED, BD);
    transpose_k<<<dim3(ED/32, BA/32), dim3(32,8)>>>(I, It, BA, ED);
    init_k<<<(BD*BA+255)/256, 256>>>(a);

    // G = B^T B  [2048 x 2048], c = B^T I_t [2048 x 128]
    gemm_nt_k<0><<<dim3(BD/64, BD/16), 128>>>(BT, BT, G, nullptr, BD, ED);
    gemm_nt_k<0><<<dim3(BA/64, BD/16), 128>>>(BT, I,  c, nullptr, BA, ED);

    // S = B B^T, then 6 renormalized squarings -> g_T0 = dir(S^64)
    gemm_nt_k<0><<<dim3(ED/64, ED/16), 128>>>(basis, basis, S, nullptr, ED, BD);
    copyN_k<<<(ED*ED+255)/256, 256>>>(S, T0, ED*ED);
    float* sq[2] = {T0, T1};
    for (int i = 0; i < 6; i++) {
        diagmax_k<<<1, 1024>>>(sq[0]);
        gemm_nt_k<3><<<dim3(ED/64, ED/16), 128>>>(sq[0], sq[0], sq[1], nullptr, ED, ED);
        float* t = sq[0]; sq[0] = sq[1]; sq[1] = t;
    }

    persist_k<<<GRID, 256>>>(basis);

    rowstats_k<<<BD, 128>>>(a, hd, l1h, out + O_HES, out + O_L1);
    gemm_nt_k<4><<<dim3(BD/64, ED/16), 128>>>(r, a, NB, basis, BD, BA);
    colnorm1_k<<<dim3(BD/256, ED/128), 256>>>(NB);
    colnorm2_k<<<(ED*BD+255)/256, 256>>>(NB, out + O_BASIS);
    copy_a_k<<<(BD*BA+255)/256, 256>>>(a, out + O_A);
    sumI2_k<<<256, 256>>>(I);
    scalarfin_k<<<1, 1>>>(se, ne, out + O_SNR);
}

// round 7
// speedup vs baseline: 1.4202x; 1.0000x over previous
#include <cuda_runtime.h>
#include <cstddef>

#define ED 1024
#define BD 2048
#define BA 128
#define NITER 500
#define LAMB_C 0.3f
#define H_C 0.005f
#define RMC 0.99f
#define LOWACT 0.001f
#define GRID 128

#define O_A     ((size_t)0)
#define O_BASIS ((size_t)(BD*BA))
#define O_HES   (O_BASIS + (size_t)ED*BD)
#define O_L1    (O_HES + BD)
#define O_SNR   (O_L1 + BD)

__device__ float g_BT[(size_t)BD*ED];
__device__ float g_It[(size_t)ED*BA];
__device__ float g_a [(size_t)BD*BA];
__device__ float g_a2[(size_t)BD*BA];
__device__ float g_c [(size_t)BD*BA];
__device__ float g_G [(size_t)BD*BD];
__device__ float g_r [(size_t)ED*BA];
__device__ float g_S [(size_t)ED*ED];
__device__ float g_T0[(size_t)ED*ED];
__device__ float g_T1[(size_t)ED*ED];
__device__ float g_NB[(size_t)ED*BD];
__device__ float g_hes[BD];
__device__ float g_nsq[BD];
__device__ float g_v[ED];
__device__ float g_w[ED];
__device__ float g_scal[8];             // 0:lam 1:eta 2:thr 3:scale 4:sumI2
__device__ unsigned g_cnt;
__device__ volatile unsigned g_gen;

__device__ __forceinline__ float sshrinkf(float v, float thr) {
    float t = fabsf(v) - thr;
    return t > 0.0f ? copysignf(t, v) : 0.0f;
}

// packed fp32 FMA: d = a*b + d, rounding identical to scalar fmaf (verified R5)
__device__ __forceinline__ void ffma2(unsigned long long &d, unsigned long long a,
                                      unsigned long long b) {
    asm("fma.rn.f32x2 %0, %1, %2, %0;" : "+l"(d) : "l"(a), "l"(b));
}
__device__ __forceinline__ float2 upk(unsigned long long v) {
    float2 f;
    asm("mov.b64 {%0, %1}, %2;" : "=f"(f.x), "=f"(f.y) : "l"(v));
    return f;
}

// ---- software grid barrier ----
__device__ __forceinline__ void gsync(unsigned gen) {
    __syncthreads();
    if (threadIdx.x == 0) {
        __threadfence();
        unsigned t = atomicAdd(&g_cnt, 1u);
        if (t == GRID - 1) {
            g_cnt = 0;
            __threadfence();
            g_gen = gen;
        } else {
            while (g_gen < gen) { }
            __threadfence();
        }
    }
    __syncthreads();
}

// ---- persistent kernel: power iteration + 500 Gram-ISTA iterations + residual ----
__global__ void __launch_bounds__(256, 1) persist_k(const float* __restrict__ basis)
{
    __shared__ __align__(16) float As[2][32][132];   // a-tile (k x 128 cols), padded
    __shared__ __align__(16) float Gs[2][32][34];    // G-tile duplicated {g,g}, padded
    __shared__ float Bsr[8][32];
    __shared__ float red1[8], red2[8];
    __shared__ float sh_b;
    const int cta = blockIdx.x, tid = threadIdx.x;
    const int w = tid >> 5, l = tid & 31;
    unsigned gen = 0;

    // ---- power iteration: 8 matvecs on dir(S^64) (g_T0), then S + Rayleigh ----
    for (int pi = 0; pi < 9; pi++) {
        const float* M = (pi < 8) ? g_T0 : g_S;
        {
            int row = cta*8 + w;
            const float* mr = M + (size_t)row*ED;
            float s = 0.f;
            for (int j = l; j < ED; j += 32) s = fmaf(mr[j], g_v[j], s);
            #pragma unroll
            for (int o = 16; o; o >>= 1) s += __shfl_xor_sync(~0u, s, o);
            if (l == 0) g_w[row] = s;
        }
        gen++; gsync(gen);
        if (cta == 0) {
            if (pi < 8) {
                float x[4], ss = 0.f;
                #pragma unroll
                for (int i = 0; i < 4; i++) { x[i] = g_w[tid*4+i]; ss = fmaf(x[i], x[i], ss); }
                #pragma unroll
                for (int o = 16; o; o >>= 1) ss += __shfl_xor_sync(~0u, ss, o);
                if (l == 0) red1[w] = ss;
                __syncthreads();
                if (tid == 0) {
                    float t = 0.f;
                    #pragma unroll
                    for (int i = 0; i < 8; i++) t += red1[i];
                    sh_b = rsqrtf(t);
                }
                __syncthreads();
                float rs = sh_b;
                #pragma unroll
                for (int i = 0; i < 4; i++) g_v[tid*4+i] = x[i]*rs;
            } else {
                float d1 = 0.f, d2 = 0.f;
                #pragma unroll
                for (int i = 0; i < 4; i++) {
                    float vv = g_v[tid*4+i], ww = g_w[tid*4+i];
                    d1 = fmaf(vv, ww, d1); d2 = fmaf(vv, vv, d2);
                }
                #pragma unroll
                for (int o = 16; o; o >>= 1) {
                    d1 += __shfl_xor_sync(~0u, d1, o);
                    d2 += __shfl_xor_sync(~0u, d2, o);
                }
                if (l == 0) { red1[w] = d1; red2[w] = d2; }
                __syncthreads();
                if (tid == 0) {
                    float a = 0.f, b = 0.f;
                    #pragma unroll
                    for (int i = 0; i < 8; i++) { a += red1[i]; b += red2[i]; }
                    float lam = a / b;
                    g_scal[0] = lam;
                    g_scal[1] = 1.0f / lam;
                    g_scal[2] = LAMB_C / lam;
                }
                __syncthreads();
            }
        }
        gen++; gsync(gen);
    }

    const float eta = g_scal[1], thr = g_scal[2];
    // micro-tile mapping: warp w -> cols [16w,16w+16); lane: cg = l&3, rp = l>>2
    const int cg = l & 3, rp = l >> 2;
    const int col0 = w*16 + cg*4;
    const int row0 = cta*16;
    // loader indices
    const int lar = tid >> 3, lac = tid & 7;       // a-tile: k-row 0..31, col-group 0..7
    const int lgr = tid >> 4, lgk = (tid & 15)*2;  // G-tile: row 0..15, k-offset 0..30
    const float* Grow = g_G + (size_t)(row0 + lgr)*BD + lgk;

    // ---- 500 Gram-ISTA iterations: a_nxt = shrink(a_cur + eta*(c - G a_cur)) ----
    for (int it = 0; it < NITER; it++) {
        const float* acur = (it & 1) ? g_a2 : g_a;
        float*       anxt = (it & 1) ? g_a  : g_a2;

        unsigned long long a00 = 0, a01 = 0, a10 = 0, a11 = 0;
        float4 rA[4]; float2 rG;

        // prefetch tile 0
        #pragma unroll
        for (int i = 0; i < 4; i++)
            rA[i] = *(const float4*)&acur[(size_t)lar*BA + 4*(lac + 8*i)];
        rG = *(const float2*)&Grow[0];
        #pragma unroll
        for (int i = 0; i < 4; i++)
            *(float4*)&As[0][lar][4*(lac + 8*i)] = rA[i];
        *(float2*)&Gs[0][lgk  ][2*lgr] = make_float2(rG.x, rG.x);
        *(float2*)&Gs[0][lgk+1][2*lgr] = make_float2(rG.y, rG.y);

        #pragma unroll 1
        for (int t = 0; t < 64; t++) {
            __syncthreads();
            if (t < 63) {
                int k0 = (t+1)*32;
                #pragma unroll
                for (int i = 0; i < 4; i++)
                    rA[i] = *(const float4*)&acur[(size_t)(k0 + lar)*BA + 4*(lac + 8*i)];
                rG = *(const float2*)&Grow[k0];
            }
            const int b = t & 1;
            #pragma unroll
            for (int kk = 0; kk < 32; kk++) {
                ulonglong2 av = *(const ulonglong2*)&As[b][kk][col0];
                unsigned long long gv0 = *(const unsigned long long*)&Gs[b][kk][2*rp];
                unsigned long long gv1 = *(const unsigned long long*)&Gs[b][kk][2*rp + 16];
                ffma2(a00, gv0, av.x); ffma2(a01, gv0, av.y);
                ffma2(a10, gv1, av.x); ffma2(a11, gv1, av.y);
            }
            if (t < 63) {
                const int nb = (t+1) & 1;
                #pragma unroll
                for (int i = 0; i < 4; i++)
                    *(float4*)&As[nb][lar][4*(lac + 8*i)] = rA[i];
                *(float2*)&Gs[nb][lgk  ][2*lgr] = make_float2(rG.x, rG.x);
                *(float2*)&Gs[nb][lgk+1][2*lgr] = make_float2(rG.y, rG.y);
            }
        }
        // epilogue: 2 rows x 4 cols per thread
        {
            int r0 = row0 + rp, r1 = row0 + rp + 8;
            float2 p00 = upk(a00), p01 = upk(a01), p10 = upk(a10), p11 = upk(a11);
            float4 ao = *(const float4*)&acur[(size_t)r0*BA + col0];
            float4 cv = *(const float4*)&g_c[(size_t)r0*BA + col0];
            float4 o;
            o.x = sshrinkf(ao.x + eta*(cv.x - p00.x), thr);
            o.y = sshrinkf(ao.y + eta*(cv.y - p00.y), thr);
            o.z = sshrinkf(ao.z + eta*(cv.z - p01.x), thr);
            o.w = sshrinkf(ao.w + eta*(cv.w - p01.y), thr);
            *(float4*)&anxt[(size_t)r0*BA + col0] = o;
            ao = *(const float4*)&acur[(size_t)r1*BA + col0];
            cv = *(const float4*)&g_c[(size_t)r1*BA + col0];
            o.x = sshrinkf(ao.x + eta*(cv.x - p10.x), thr);
            o.y = sshrinkf(ao.y + eta*(cv.y - p10.y), thr);
            o.z = sshrinkf(ao.z + eta*(cv.z - p11.x), thr);
            o.w = sshrinkf(ao.w + eta*(cv.w - p11.y), thr);
            *(float4*)&anxt[(size_t)r1*BA + col0] = o;
        }
        gen++; gsync(gen);
    }

    // ---- final residual: r(8 rows/CTA) = It - basis * a, K=2048 (one-shot) ----
    {
        const int rrow = cta*8 + w;     // warp w -> one row
        float racc0 = 0.f, racc1 = 0.f, racc2 = 0.f, racc3 = 0.f;
        for (int t = 0; t < 64; t++) {
            int k0 = t*32;
            float4 rAv[4];
            #pragma unroll
            for (int i = 0; i < 4; i++)
                rAv[i] = *(const float4*)&g_a[(size_t)(k0 + lar)*BA + 4*(lac + 8*i)];
            float rB = basis[(size_t)rrow*BD + k0 + l];
            __syncthreads();
            #pragma unroll
            for (int i = 0; i < 4; i++)
                *(float4*)&As[0][lar][4*(lac + 8*i)] = rAv[i];
            Bsr[w][l] = rB;
            __syncthreads();
            #pragma unroll 4
            for (int kk = 0; kk < 32; kk++) {
                float bb = Bsr[w][kk];
                float4 avv = *(const float4*)&As[0][kk][l*4];
                racc0 = fmaf(bb, avv.x, racc0);
                racc1 = fmaf(bb, avv.y, racc1);
                racc2 = fmaf(bb, avv.z, racc2);
                racc3 = fmaf(bb, avv.w, racc3);
            }
        }
        float4 iv = *(const float4*)&g_It[(size_t)rrow*BA + l*4];
        *(float4*)&g_r[(size_t)rrow*BA + l*4] =
            make_float4(iv.x - racc0, iv.y - racc1, iv.z - racc2, iv.w - racc3);
    }
}

// ---------------- NT GEMM (prologue/epilogue nodes) ----------------
// EPI 0: store   EPI 3: store*scale^2   EPI 4: NB = Aux + (H/BA)*acc/(hes+eps)
template<int EPI>
__global__ void __launch_bounds__(128, 2) gemm_nt_k(
    const float* __restrict__ A, const float* __restrict__ Bm,
    float* __restrict__ C, const float* __restrict__ Aux,
    int Nh, int Kh)
{
    __shared__ float As[2][64][18];
    __shared__ float Bs[2][64][68];
    const int tid = threadIdx.x;
    const int tx = tid & 15, ty = tid >> 4;
    const float* Ab = A + (size_t)blockIdx.y * 16 * Kh;
    const float* Bb = Bm + (size_t)blockIdx.x * 64 * Kh;
    const int ar0 = tid >> 4, ar1 = (tid + 128) >> 4, ak = (tid & 15) * 4;

    float4 ra0, ra1, rb[8];
    float acc[2][4] = {{0,0,0,0},{0,0,0,0}};

    ra0 = *(const float4*)(Ab + (size_t)ar0*Kh + ak);
    ra1 = *(const float4*)(Ab + (size_t)ar1*Kh + ak);
    #pragma unroll
    for (int i = 0; i < 8; i++) {
        int q = tid + i*128;
        rb[i] = *(const float4*)(Bb + (size_t)(q>>4)*Kh + (q&15)*4);
    }
    As[0][ak+0][ar0]=ra0.x; As[0][ak+1][ar0]=ra0.y; As[0][ak+2][ar0]=ra0.z; As[0][ak+3][ar0]=ra0.w;
    As[0][ak+0][ar1]=ra1.x; As[0][ak+1][ar1]=ra1.y; As[0][ak+2][ar1]=ra1.z; As[0][ak+3][ar1]=ra1.w;
    #pragma unroll
    for (int i = 0; i < 8; i++) {
        int q = tid + i*128; int n = q>>4; int kq = (q&15)*4;
        Bs[0][kq+0][n]=rb[i].x; Bs[0][kq+1][n]=rb[i].y; Bs[0][kq+2][n]=rb[i].z; Bs[0][kq+3][n]=rb[i].w;
    }

    const int T = Kh >> 6;
    for (int t = 0; t < T; t++) {
        __syncthreads();
        if (t + 1 < T) {
            int k0 = (t+1) * 64;
            ra0 = *(const float4*)(Ab + (size_t)ar0*Kh + k0 + ak);
            ra1 = *(const float4*)(Ab + (size_t)ar1*Kh + k0 + ak);
            #pragma unroll
            for (int i = 0; i < 8; i++) {
                int q = tid + i*128;
                rb[i] = *(const float4*)(Bb + (size_t)(q>>4)*Kh + k0 + (q&15)*4);
            }
        }
        const int buf = t & 1;
        #pragma unroll
        for (int kk = 0; kk < 64; kk++) {
            float2 av = *(const float2*)&As[buf][kk][ty*2];
            float4 bv = *(const float4*)&Bs[buf][kk][tx*4];
            acc[0][0]=fmaf(av.x,bv.x,acc[0][0]); acc[0][1]=fmaf(av.x,bv.y,acc[0][1]);
            acc[0][2]=fmaf(av.x,bv.z,acc[0][2]); acc[0][3]=fmaf(av.x,bv.w,acc[0][3]);
            acc[1][0]=fmaf(av.y,bv.x,acc[1][0]); acc[1][1]=fmaf(av.y,bv.y,acc[1][1]);
            acc[1][2]=fmaf(av.y,bv.z,acc[1][2]); acc[1][3]=fmaf(av.y,bv.w,acc[1][3]);
        }
        if (t + 1 < T) {
            const int nb = (t+1) & 1;
            As[nb][ak+0][ar0]=ra0.x; As[nb][ak+1][ar0]=ra0.y; As[nb][ak+2][ar0]=ra0.z; As[nb][ak+3][ar0]=ra0.w;
            As[nb][ak+0][ar1]=ra1.x; As[nb][ak+1][ar1]=ra1.y; As[nb][ak+2][ar1]=ra1.z; As[nb][ak+3][ar1]=ra1.w;
            #pragma unroll
            for (int i = 0; i < 8; i++) {
                int q = tid + i*128; int n = q>>4; int kq = (q&15)*4;
                Bs[nb][kq+0][n]=rb[i].x; Bs[nb][kq+1][n]=rb[i].y; Bs[nb][kq+2][n]=rb[i].z; Bs[nb][kq+3][n]=rb[i].w;
            }
        }
    }

    const int gm = blockIdx.y*16 + ty*2;
    const int gn = blockIdx.x*64 + tx*4;
    if (EPI == 0) {
        #pragma unroll
        for (int mi = 0; mi < 2; mi++)
            *(float4*)(C + (size_t)(gm+mi)*Nh + gn) =
                make_float4(acc[mi][0],acc[mi][1],acc[mi][2],acc[mi][3]);
    } else if (EPI == 3) {
        const float s2 = g_scal[3] * g_scal[3];
        #pragma unroll
        for (int mi = 0; mi < 2; mi++)
            *(float4*)(C + (size_t)(gm+mi)*Nh + gn) =
                make_float4(acc[mi][0]*s2,acc[mi][1]*s2,acc[mi][2]*s2,acc[mi][3]*s2);
    } else {
        #pragma unroll
        for (int mi = 0; mi < 2; mi++)
            #pragma unroll
            for (int ni = 0; ni < 4; ni++) {
                int col = gn + ni;
                C[(size_t)(gm+mi)*Nh + col] = Aux[(size_t)(gm+mi)*Nh + col] +
                    (H_C/(float)BA) * acc[mi][ni] / (g_hes[col] + LOWACT);
            }
    }
}

// ---------------- helpers ----------------
__global__ void transpose_k(const float* __restrict__ in, float* __restrict__ out,
                            int rows, int cols)
{
    __shared__ float sm[32][33];
    int bx = blockIdx.x*32, by = blockIdx.y*32;
    int tx = threadIdx.x, ty = threadIdx.y;
    #pragma unroll
    for (int j = 0; j < 32; j += 8)
        sm[ty+j][tx] = in[(size_t)(by+ty+j)*cols + bx+tx];
    __syncthreads();
    #pragma unroll
    for (int j = 0; j < 32; j += 8)
        out[(size_t)(bx+ty+j)*rows + by+tx] = sm[tx][ty+j];
}

__global__ void init_k(float* a) {
    int idx = blockIdx.x*blockDim.x + threadIdx.x;
    if (idx < BD*BA) a[idx] = 0.0f;
    if (idx < ED) g_v[idx] = 1.0f;
    if (idx == 0) { g_scal[4] = 0.0f; g_cnt = 0; g_gen = 0; }
}

__global__ void copyN_k(const float* __restrict__ in, float* __restrict__ out, int n) {
    int i = blockIdx.x*256 + threadIdx.x;
    if (i < n) out[i] = in[i];
}

__global__ void diagmax_k(const float* __restrict__ T) {
    __shared__ float red[32];
    int tid = threadIdx.x;
    float m = fabsf(T[(size_t)tid*ED + tid]);
    #pragma unroll
    for (int o = 16; o; o >>= 1) m = fmaxf(m, __shfl_xor_sync(~0u, m, o));
    if ((tid&31)==0) red[tid>>5] = m;
    __syncthreads();
    if (tid < 32) {
        float mm = red[tid];
        #pragma unroll
        for (int o = 16; o; o >>= 1) mm = fmaxf(mm, __shfl_xor_sync(~0u, mm, o));
        if (tid == 0) g_scal[3] = 1.0f / mm;
    }
}

__global__ void rowstats_k(const float* __restrict__ a, const float* __restrict__ hd,
                           const float* __restrict__ l1h,
                           float* __restrict__ out_hes, float* __restrict__ out_l1)
{
    __shared__ float s1s[4], s2s[4];
    int m = blockIdx.x, tid = threadIdx.x;
    float av = a[(size_t)m*BA + tid];
    float s1 = fabsf(av), s2 = av*av;
    #pragma unroll
    for (int o = 16; o; o >>= 1) {
        s1 += __shfl_xor_sync(~0u, s1, o);
        s2 += __shfl_xor_sync(~0u, s2, o);
    }
    if ((tid&31)==0) { s1s[tid>>5]=s1; s2s[tid>>5]=s2; }
    __syncthreads();
    if (tid == 0) {
        float t1 = s1s[0]+s1s[1]+s1s[2]+s1s[3];
        float t2 = s2s[0]+s2s[1]+s2s[2]+s2s[3];
        float he = hd[m]*RMC + t2*(1.0f/(BA*100.0f));
        out_l1[m] = l1h[m]*RMC + t1*(1.0f/(BA*100.0f));
        out_hes[m] = he;
        g_hes[m] = he;
        g_nsq[m] = 0.0f;
    }
}

__global__ void colnorm1_k(const float* __restrict__ NB) {
    int col = blockIdx.x*256 + threadIdx.x;
    int r0 = blockIdx.y*128;
    float s = 0.0f;
    for (int r = r0; r < r0+128; r++) {
        float v = NB[(size_t)r*BD + col];
        s = fmaf(v, v, s);
    }
    atomicAdd(&g_nsq[col], s);
}

__global__ void colnorm2_k(const float* __restrict__ NB, float* __restrict__ out) {
    int i = blockIdx.x*blockDim.x + threadIdx.x;
    if (i < ED*BD) out[i] = NB[i] * rsqrtf(g_nsq[i & (BD-1)]);
}

__global__ void copy_a_k(const float* __restrict__ a, float* __restrict__ out) {
    int i = blockIdx.x*blockDim.x + threadIdx.x;
    if (i < BD*BA) out[i] = a[i];
}

__global__ void sumI2_k(const float* __restrict__ I) {
    __shared__ float red[8];
    int tid = threadIdx.x;
    float s = 0.0f;
    for (int i = blockIdx.x*blockDim.x + tid; i < ED*BA; i += gridDim.x*blockDim.x) {
        float v = I[i];
        s = fmaf(v, v, s);
    }
    #pragma unroll
    for (int o = 16; o; o >>= 1) s += __shfl_xor_sync(~0u, s, o);
    if ((tid&31)==0) red[tid>>5] = s;
    __syncthreads();
    if (tid == 0) {
        float t = 0.0f;
        #pragma unroll
        for (int i = 0; i < 8; i++) t += red[i];
        atomicAdd(&g_scal[4], t);
    }
}

__global__ void scalarfin_k(const float* __restrict__ se, const float* __restrict__ ne,
                            float* __restrict__ out_snr)
{
    float ns = se[0]*RMC + g_scal[4]*0.01f;
    out_snr[0] = ns / (ne[0]*RMC);
}

extern "C" void kernel_launch(void* const* d_in, const int* in_sizes, int n_in,
                              void* d_out, int out_size)
{
    const float* I     = (const float*)d_in[0];
    const float* basis = (const float*)d_in[1];
    const float* hd    = (const float*)d_in[2];
    const float* l1h   = (const float*)d_in[3];
    const float* se    = (const float*)d_in[4];
    const float* ne    = (const float*)d_in[5];
    float* out = (float*)d_out;

    float *BT,*It,*a,*r,*S,*T0,*T1,*NB,*G,*c;
    cudaGetSymbolAddress((void**)&BT, g_BT);
    cudaGetSymbolAddress((void**)&It, g_It);
    cudaGetSymbolAddress((void**)&a,  g_a);
    cudaGetSymbolAddress((void**)&r,  g_r);
    cudaGetSymbolAddress((void**)&S,  g_S);
    cudaGetSymbolAddress((void**)&T0, g_T0);
    cudaGetSymbolAddress((void**)&T1, g_T1);
    cudaGetSymbolAddress((void**)&NB, g_NB);
    cudaGetSymbolAddress((void**)&G,  g_G);
    cudaGetSymbolAddress((void**)&c,  g_c);

    transpose_k<<<dim3(BD/32, ED/32), dim3(32,8)>>>(basis, BT, ED, BD);
    transpose_k<<<dim3(ED/32, BA/32), dim3(32,8)>>>(I, It, BA, ED);
    init_k<<<(BD*BA+255)/256, 256>>>(a);

    // G = B^T B  [2048 x 2048], c = B^T I_t [2048 x 128]
    gemm_nt_k<0><<<dim3(BD/64, BD/16), 128>>>(BT, BT, G, nullptr, BD, ED);
    gemm_nt_k<0><<<dim3(BA/64, BD/16), 128>>>(BT, I,  c, nullptr, BA, ED);

    // S = B B^T, then 6 renormalized squarings -> g_T0 = dir(S^64)
    gemm_nt_k<0><<<dim3(ED/64, ED/16), 128>>>(basis, basis, S, nullptr, ED, BD);
    copyN_k<<<(ED*ED+255)/256, 256>>>(S, T0, ED*ED);
    float* sq[2] = {T0, T1};
    for (int i = 0; i < 6; i++) {
        diagmax_k<<<1, 1024>>>(sq[0]);
        gemm_nt_k<3><<<dim3(ED/64, ED/16), 128>>>(sq[0], sq[0], sq[1], nullptr, ED, ED);
        float* t = sq[0]; sq[0] = sq[1]; sq[1] = t;
    }

    persist_k<<<GRID, 256>>>(basis);

    rowstats_k<<<BD, 128>>>(a, hd, l1h, out + O_HES, out + O_L1);
    gemm_nt_k<4><<<dim3(BD/64, ED/16), 128>>>(r, a, NB, basis, BD, BA);
    colnorm1_k<<<dim3(BD/256, ED/128), 256>>>(NB);
    colnorm2_k<<<(ED*BD+255)/256, 256>>>(NB, out + O_BASIS);
    copy_a_k<<<(BD*BA+255)/256, 256>>>(a, out + O_A);
    sumI2_k<<<256, 256>>>(I);
    scalarfin_k<<<1, 1>>>(se, ne, out + O_SNR);
}

// round 10
// speedup vs baseline: 3.8349x; 2.7002x over previous
#include <cuda_runtime.h>
#include <cuda_bf16.h>
#include <cstdint>
#include <cstddef>

#define ED 1024
#define BD 2048
#define BA 128
#define NITER 500
#define LAMB_C 0.3f
#define H_C 0.005f
#define RMC 0.99f
#define LOWACT 0.001f
#define GRIDP 128

#define O_A     ((size_t)0)
#define O_BASIS ((size_t)(BD*BA))
#define O_HES   (O_BASIS + (size_t)ED*BD)
#define O_L1    (O_HES + BD)
#define O_SNR   (O_L1 + BD)

// dynamic smem byte offsets (row stride 144B = 72 bf16, conflict-free ldmatrix)
#define GH_O 0
#define GL_O 4608
#define AH_O 9216
#define AL_O 18432
#define BUFS 28672
#define DYN  (2*BUFS)

__device__ float g_BT[(size_t)BD*ED];
__device__ float g_It[(size_t)ED*BA];
__device__ float g_a [(size_t)BD*BA];
__device__ float g_a2[(size_t)BD*BA];
__device__ float g_c [(size_t)BD*BA];
__device__ float g_G [(size_t)BD*BD];
__device__ float g_r [(size_t)ED*BA];
__device__ float g_S [(size_t)ED*ED];
__device__ float g_T0[(size_t)ED*ED];
__device__ float g_T1[(size_t)ED*ED];
__device__ float g_NB[(size_t)ED*BD];
__device__ __nv_bfloat16 g_Gh[(size_t)BD*BD];
__device__ __nv_bfloat16 g_Gl[(size_t)BD*BD];
__device__ __nv_bfloat16 g_ah0[(size_t)BD*BA];
__device__ __nv_bfloat16 g_ah1[(size_t)BD*BA];
__device__ __nv_bfloat16 g_al0[(size_t)BD*BA];
__device__ __nv_bfloat16 g_al1[(size_t)BD*BA];
__device__ float g_hes[BD];
__device__ float g_nsq[BD];
__device__ float g_v[ED];
__device__ float g_w[ED];
__device__ float g_scal[8];
__device__ unsigned g_cnt;
__device__ volatile unsigned g_gen;

__device__ __forceinline__ float sshrinkf(float v, float thr) {
    float t = fabsf(v) - thr;
    return t > 0.0f ? copysignf(t, v) : 0.0f;
}
__device__ __forceinline__ uint32_t smem_u32(const void* p) {
    uint32_t a;
    asm("{ .reg .u64 t; cvta.to.shared.u64 t, %1; cvt.u32.u64 %0, t; }" : "=r"(a) : "l"(p));
    return a;
}
#define LDSM4(r, ad) asm volatile( \
    "ldmatrix.sync.aligned.m8n8.x4.shared.b16 {%0,%1,%2,%3},[%4];" \
    : "=r"((r)[0]),"=r"((r)[1]),"=r"((r)[2]),"=r"((r)[3]) : "r"(ad))
#define LDSM4T(r, ad) asm volatile( \
    "ldmatrix.sync.aligned.m8n8.x4.trans.shared.b16 {%0,%1,%2,%3},[%4];" \
    : "=r"((r)[0]),"=r"((r)[1]),"=r"((r)[2]),"=r"((r)[3]) : "r"(ad))
#define MMA16816(c, a, b0, b1) asm volatile( \
    "mma.sync.aligned.m16n8k16.row.col.f32.bf16.bf16.f32 " \
    "{%0,%1,%2,%3},{%4,%5,%6,%7},{%8,%9},{%0,%1,%2,%3};" \
    : "+f"((c)[0]),"+f"((c)[1]),"+f"((c)[2]),"+f"((c)[3]) \
    : "r"((a)[0]),"r"((a)[1]),"r"((a)[2]),"r"((a)[3]),"r"(b0),"r"(b1))

__device__ __forceinline__ void gsync(unsigned gen) {
    __syncthreads();
    if (threadIdx.x == 0) {
        __threadfence();
        unsigned t = atomicAdd(&g_cnt, 1u);
        if (t == GRIDP - 1) { g_cnt = 0; __threadfence(); g_gen = gen; }
        else { while (g_gen < gen) { } __threadfence(); }
    }
    __syncthreads();
}

// ---- persistent: power iteration + 500 mma.sync Gram-ISTA iters + residual ----
__global__ void __launch_bounds__(256, 1) persist3_k(const float* __restrict__ basis)
{
    extern __shared__ char dsm[];
    __shared__ float red1[8], red2[8];
    __shared__ float sh_b;
    const int cta = blockIdx.x, tid = threadIdx.x;
    const int w = tid >> 5, l = tid & 31;
    unsigned gen = 0;
    const uint32_t smu = smem_u32(dsm);

    // ---- power iteration: 8 matvecs on dir(S^64) (g_T0), then S + Rayleigh ----
    for (int pi = 0; pi < 9; pi++) {
        const float* M = (pi < 8) ? g_T0 : g_S;
        {
            int rw = cta*8 + w;
            const float* mr = M + (size_t)rw*ED;
            float s = 0.f;
            for (int j = l; j < ED; j += 32) s = fmaf(mr[j], g_v[j], s);
            #pragma unroll
            for (int o = 16; o; o >>= 1) s += __shfl_xor_sync(~0u, s, o);
            if (l == 0) g_w[rw] = s;
        }
        gen++; gsync(gen);
        if (cta == 0) {
            if (pi < 8) {
                float x[4], ss = 0.f;
                #pragma unroll
                for (int i = 0; i < 4; i++) { x[i] = g_w[tid*4+i]; ss = fmaf(x[i], x[i], ss); }
                #pragma unroll
                for (int o = 16; o; o >>= 1) ss += __shfl_xor_sync(~0u, ss, o);
                if (l == 0) red1[w] = ss;
                __syncthreads();
                if (tid == 0) {
                    float t = 0.f;
                    for (int i = 0; i < 8; i++) t += red1[i];
                    sh_b = rsqrtf(t);
                }
                __syncthreads();
                float rs = sh_b;
                #pragma unroll
                for (int i = 0; i < 4; i++) g_v[tid*4+i] = x[i]*rs;
            } else {
                float d1 = 0.f, d2 = 0.f;
                #pragma unroll
                for (int i = 0; i < 4; i++) {
                    float vv = g_v[tid*4+i], ww = g_w[tid*4+i];
                    d1 = fmaf(vv, ww, d1); d2 = fmaf(vv, vv, d2);
                }
                #pragma unroll
                for (int o = 16; o; o >>= 1) {
                    d1 += __shfl_xor_sync(~0u, d1, o);
                    d2 += __shfl_xor_sync(~0u, d2, o);
                }
                if (l == 0) { red1[w] = d1; red2[w] = d2; }
                __syncthreads();
                if (tid == 0) {
                    float a = 0.f, b = 0.f;
                    for (int i = 0; i < 8; i++) { a += red1[i]; b += red2[i]; }
                    float lam = a / b;
                    g_scal[0] = lam; g_scal[1] = 1.0f/lam; g_scal[2] = LAMB_C/lam;
                }
                __syncthreads();
            }
        }
        gen++; gsync(gen);
    }

    const float eta = g_scal[1], thr = g_scal[2];
    const int mt = cta >> 1, nh = cta & 1;      // 64 M-tiles of 32, 2 N-halves
    const int wm = w >> 2, wn = w & 3;          // warp grid 2x4, warp tile 16x16
    // ldmatrix per-lane base offsets (bytes within buffer)
    const uint32_t adA = (uint32_t)(wm*16 + (l & 15))*144 + ((l >> 4)*16);
    const uint32_t adB = (uint32_t)((l & 7) + ((l >> 3) & 1)*8)*144 + (wn*32 + (l >> 4)*16);
    // loader indices
    const int gur = tid >> 3, guq = tid & 7;    // G: row 0..31, 16B-quad 0..7
    const __nv_bfloat16* GhR = g_Gh + (size_t)(mt*32 + gur)*BD + guq*8;
    const __nv_bfloat16* GlR = g_Gl + (size_t)(mt*32 + gur)*BD + guq*8;

    for (int it = 0; it < NITER; it++) {
        const int cur = it & 1;
        const float* acur = cur ? g_a2 : g_a;
        float*       anxt = cur ? g_a  : g_a2;
        const __nv_bfloat16* ahc = cur ? g_ah1 : g_ah0;
        const __nv_bfloat16* alc = cur ? g_al1 : g_al0;
        __nv_bfloat16* ahn = cur ? g_ah0 : g_ah1;
        __nv_bfloat16* aln = cur ? g_al0 : g_al1;

        float acc0[4] = {0,0,0,0}, acc1[4] = {0,0,0,0};
        uint4 rGh, rGl, rh0, rh1, rl0, rl1;

        // prefetch chunk 0
        {
            rGh = *(const uint4*)GhR;
            rGl = *(const uint4*)GlR;
            const __nv_bfloat16* p = ahc + (size_t)gur*BA + nh*64 + guq*8;
            rh0 = *(const uint4*)p;
            rh1 = *(const uint4*)(p + 32*BA);
            const __nv_bfloat16* q = alc + (size_t)gur*BA + nh*64 + guq*8;
            rl0 = *(const uint4*)q;
            rl1 = *(const uint4*)(q + 32*BA);
        }

        #pragma unroll 1
        for (int t = 0; t < 32; t++) {
            const int b = t & 1;
            char* sb = dsm + b*BUFS;
            // store current chunk
            *(uint4*)(sb + GH_O + gur*144 + guq*16) = rGh;
            *(uint4*)(sb + GL_O + gur*144 + guq*16) = rGl;
            *(uint4*)(sb + AH_O + gur*144 + guq*16) = rh0;
            *(uint4*)(sb + AH_O + (gur+32)*144 + guq*16) = rh1;
            *(uint4*)(sb + AL_O + gur*144 + guq*16) = rl0;
            *(uint4*)(sb + AL_O + (gur+32)*144 + guq*16) = rl1;
            __syncthreads();
            if (t < 31) {
                int kc = (t+1)*64;
                rGh = *(const uint4*)(GhR + kc);
                rGl = *(const uint4*)(GlR + kc);
                const __nv_bfloat16* p = ahc + (size_t)(kc + gur)*BA + nh*64 + guq*8;
                rh0 = *(const uint4*)p;
                rh1 = *(const uint4*)(p + 32*BA);
                const __nv_bfloat16* q = alc + (size_t)(kc + gur)*BA + nh*64 + guq*8;
                rl0 = *(const uint4*)q;
                rl1 = *(const uint4*)(q + 32*BA);
            }
            const uint32_t base = smu + (uint32_t)b*BUFS;
            #pragma unroll
            for (int kq = 0; kq < 4; kq++) {
                uint32_t fah[4], fal[4], fbh[4], fbl[4];
                LDSM4(fah, base + GH_O + kq*32 + adA);
                LDSM4(fal, base + GL_O + kq*32 + adA);
                LDSM4T(fbh, base + AH_O + kq*16*144 + adB);
                LDSM4T(fbl, base + AL_O + kq*16*144 + adB);
                MMA16816(acc0, fah, fbh[0], fbh[1]);
                MMA16816(acc1, fah, fbh[2], fbh[3]);
                MMA16816(acc0, fah, fbl[0], fbl[1]);
                MMA16816(acc1, fah, fbl[2], fbl[3]);
                MMA16816(acc0, fal, fbh[0], fbh[1]);
                MMA16816(acc1, fal, fbh[2], fbh[3]);
            }
        }
        __syncthreads();

        // epilogue: c-frag mapping (d0,d1)->(row,col..col+1), (d2,d3)->(row+8,..)
        {
            #pragma unroll
            for (int nt = 0; nt < 2; nt++) {
                const float* ap = nt ? acc1 : acc0;
                int gc = nh*64 + wn*16 + nt*8 + (l & 3)*2;
                #pragma unroll
                for (int rr = 0; rr < 2; rr++) {
                    int gr = mt*32 + wm*16 + (l >> 2) + rr*8;
                    size_t idx = (size_t)gr*BA + gc;
                    float2 ao = *(const float2*)&acur[idx];
                    float2 cv = *(const float2*)&g_c[idx];
                    float vx = sshrinkf(ao.x + eta*(cv.x - ap[rr*2+0]), thr);
                    float vy = sshrinkf(ao.y + eta*(cv.y - ap[rr*2+1]), thr);
                    *(float2*)&anxt[idx] = make_float2(vx, vy);
                    __nv_bfloat162 hp, lp;
                    hp.x = __float2bfloat16(vx);
                    hp.y = __float2bfloat16(vy);
                    lp.x = __float2bfloat16(vx - __bfloat162float(hp.x));
                    lp.y = __float2bfloat16(vy - __bfloat162float(hp.y));
                    *(__nv_bfloat162*)&ahn[idx] = hp;
                    *(__nv_bfloat162*)&aln[idx] = lp;
                }
            }
        }
        gen++; gsync(gen);
    }

    // ---- final residual: r = It - basis*a ; warp -> one row (128x8 = 1024) ----
    {
        const int rw = cta*8 + w;
        float4 racc = make_float4(0.f, 0.f, 0.f, 0.f);
        float* aS = (float*)dsm;                  // [32][132]
        float* bS = (float*)(dsm + 17024);        // [8][32]
        for (int t = 0; t < 64; t++) {
            int k0 = t*32;
            float4 rv[4];
            #pragma unroll
            for (int i = 0; i < 4; i++) {
                int u = tid*4 + i, rr = u >> 5, q = u & 31;
                rv[i] = *(const float4*)&g_a[(size_t)(k0 + rr)*BA + q*4];
            }
            float bb = basis[(size_t)rw*BD + k0 + l];
            __syncthreads();
            #pragma unroll
            for (int i = 0; i < 4; i++) {
                int u = tid*4 + i, rr = u >> 5, q = u & 31;
                *(float4*)&aS[rr*132 + q*4] = rv[i];
            }
            bS[w*32 + l] = bb;
            __syncthreads();
            #pragma unroll 8
            for (int kk = 0; kk < 32; kk++) {
                float b_ = bS[w*32 + kk];
                float4 av = *(const float4*)&aS[kk*132 + l*4];
                racc.x = fmaf(b_, av.x, racc.x);
                racc.y = fmaf(b_, av.y, racc.y);
                racc.z = fmaf(b_, av.z, racc.z);
                racc.w = fmaf(b_, av.w, racc.w);
            }
        }
        float4 iv = *(const float4*)&g_It[(size_t)rw*BA + l*4];
        *(float4*)&g_r[(size_t)rw*BA + l*4] =
            make_float4(iv.x-racc.x, iv.y-racc.y, iv.z-racc.z, iv.w-racc.w);
    }
}

// ---- NT GEMM: C[M,N] = A[M,K]*B[N,K]^T. EPI 0:store 3:*s^2 4:basis-update ----
template<int EPI>
__global__ void __launch_bounds__(128, 2) gemm_nt_k(
    const float* __restrict__ A, const float* __restrict__ Bm,
    float* __restrict__ C, const float* __restrict__ Aux, int Nh, int Kh)
{
    __shared__ float As[2][64][18];
    __shared__ float Bs[2][64][68];
    const int tid = threadIdx.x;
    const int tx = tid & 15, ty = tid >> 4;
    const float* Ab = A + (size_t)blockIdx.y * 16 * Kh;
    const float* Bb = Bm + (size_t)blockIdx.x * 64 * Kh;
    const int ar0 = tid >> 4, ar1 = (tid + 128) >> 4, ak = (tid & 15) * 4;
    float4 ra0, ra1, rb[8];
    float acc[2][4] = {{0,0,0,0},{0,0,0,0}};

    ra0 = *(const float4*)(Ab + (size_t)ar0*Kh + ak);
    ra1 = *(const float4*)(Ab + (size_t)ar1*Kh + ak);
    #pragma unroll
    for (int i = 0; i < 8; i++) {
        int q = tid + i*128;
        rb[i] = *(const float4*)(Bb + (size_t)(q>>4)*Kh + (q&15)*4);
    }
    As[0][ak+0][ar0]=ra0.x; As[0][ak+1][ar0]=ra0.y; As[0][ak+2][ar0]=ra0.z; As[0][ak+3][ar0]=ra0.w;
    As[0][ak+0][ar1]=ra1.x; As[0][ak+1][ar1]=ra1.y; As[0][ak+2][ar1]=ra1.z; As[0][ak+3][ar1]=ra1.w;
    #pragma unroll
    for (int i = 0; i < 8; i++) {
        int q = tid + i*128; int n = q>>4; int kq = (q&15)*4;
        Bs[0][kq+0][n]=rb[i].x; Bs[0][kq+1][n]=rb[i].y; Bs[0][kq+2][n]=rb[i].z; Bs[0][kq+3][n]=rb[i].w;
    }
    const int T = Kh >> 6;
    for (int t = 0; t < T; t++) {
        __syncthreads();
        if (t + 1 < T) {
            int k0 = (t+1) * 64;
            ra0 = *(const float4*)(Ab + (size_t)ar0*Kh + k0 + ak);
            ra1 = *(const float4*)(Ab + (size_t)ar1*Kh + k0 + ak);
            #pragma unroll
            for (int i = 0; i < 8; i++) {
                int q = tid + i*128;
                rb[i] = *(const float4*)(Bb + (size_t)(q>>4)*Kh + k0 + (q&15)*4);
            }
        }
        const int buf = t & 1;
        #pragma unroll
        for (int kk = 0; kk < 64; kk++) {
            float2 av = *(const float2*)&As[buf][kk][ty*2];
            float4 bv = *(const float4*)&Bs[buf][kk][tx*4];
            acc[0][0]=fmaf(av.x,bv.x,acc[0][0]); acc[0][1]=fmaf(av.x,bv.y,acc[0][1]);
            acc[0][2]=fmaf(av.x,bv.z,acc[0][2]); acc[0][3]=fmaf(av.x,bv.w,acc[0][3]);
            acc[1][0]=fmaf(av.y,bv.x,acc[1][0]); acc[1][1]=fmaf(av.y,bv.y,acc[1][1]);
            acc[1][2]=fmaf(av.y,bv.z,acc[1][2]); acc[1][3]=fmaf(av.y,bv.w,acc[1][3]);
        }
        if (t + 1 < T) {
            const int nb = (t+1) & 1;
            As[nb][ak+0][ar0]=ra0.x; As[nb][ak+1][ar0]=ra0.y; As[nb][ak+2][ar0]=ra0.z; As[nb][ak+3][ar0]=ra0.w;
            As[nb][ak+0][ar1]=ra1.x; As[nb][ak+1][ar1]=ra1.y; As[nb][ak+2][ar1]=ra1.z; As[nb][ak+3][ar1]=ra1.w;
            #pragma unroll
            for (int i = 0; i < 8; i++) {
                int q = tid + i*128; int n = q>>4; int kq = (q&15)*4;
                Bs[nb][kq+0][n]=rb[i].x; Bs[nb][kq+1][n]=rb[i].y; Bs[nb][kq+2][n]=rb[i].z; Bs[nb][kq+3][n]=rb[i].w;
            }
        }
    }
    const int gm = blockIdx.y*16 + ty*2;
    const int gn = blockIdx.x*64 + tx*4;
    if (EPI == 0) {
        #pragma unroll
        for (int mi = 0; mi < 2; mi++)
            *(float4*)(C + (size_t)(gm+mi)*Nh + gn) =
                make_float4(acc[mi][0],acc[mi][1],acc[mi][2],acc[mi][3]);
    } else if (EPI == 3) {
        const float s2 = g_scal[3] * g_scal[3];
        #pragma unroll
        for (int mi = 0; mi < 2; mi++)
            *(float4*)(C + (size_t)(gm+mi)*Nh + gn) =
                make_float4(acc[mi][0]*s2,acc[mi][1]*s2,acc[mi][2]*s2,acc[mi][3]*s2);
    } else {
        #pragma unroll
        for (int mi = 0; mi < 2; mi++)
            #pragma unroll
            for (int ni = 0; ni < 4; ni++) {
                int col = gn + ni;
                C[(size_t)(gm+mi)*Nh + col] = Aux[(size_t)(gm+mi)*Nh + col] +
                    (H_C/(float)BA) * acc[mi][ni] / (g_hes[col] + LOWACT);
            }
    }
}

__global__ void transpose_k(const float* __restrict__ in, float* __restrict__ out,
                            int rows, int cols)
{
    __shared__ float sm[32][33];
    int bx = blockIdx.x*32, by = blockIdx.y*32;
    int tx = threadIdx.x, ty = threadIdx.y;
    #pragma unroll
    for (int j = 0; j < 32; j += 8)
        sm[ty+j][tx] = in[(size_t)(by+ty+j)*cols + bx+tx];
    __syncthreads();
    #pragma unroll
    for (int j = 0; j < 32; j += 8)
        out[(size_t)(bx+ty+j)*rows + by+tx] = sm[tx][ty+j];
}

__global__ void init_k() {
    int idx = blockIdx.x*256 + threadIdx.x;
    if (idx < BD*BA) {
        g_a[idx] = 0.0f;
        g_ah0[idx] = __float2bfloat16(0.0f);
        g_al0[idx] = __float2bfloat16(0.0f);
    }
    if (idx < ED) g_v[idx] = 1.0f;
    if (idx == 0) { g_scal[4] = 0.0f; g_cnt = 0; g_gen = 0; }
}

__global__ void g2bf_k() {
    size_t idx = (size_t)blockIdx.x*256 + threadIdx.x;
    float g = g_G[idx];
    __nv_bfloat16 h = __float2bfloat16(g);
    g_Gh[idx] = h;
    g_Gl[idx] = __float2bfloat16(g - __bfloat162float(h));
}

__global__ void copyN_k(const float* __restrict__ in, float* __restrict__ out, int n) {
    int i = blockIdx.x*256 + threadIdx.x;
    if (i < n) out[i] = in[i];
}

__global__ void diagmax_k(const float* __restrict__ T) {
    __shared__ float red[32];
    int tid = threadIdx.x;
    float m = fabsf(T[(size_t)tid*ED + tid]);
    #pragma unroll
    for (int o = 16; o; o >>= 1) m = fmaxf(m, __shfl_xor_sync(~0u, m, o));
    if ((tid&31)==0) red[tid>>5] = m;
    __syncthreads();
    if (tid < 32) {
        float mm = red[tid];
        #pragma unroll
        for (int o = 16; o; o >>= 1) mm = fmaxf(mm, __shfl_xor_sync(~0u, mm, o));
        if (tid == 0) g_scal[3] = 1.0f / mm;
    }
}

__global__ void rowstats_k(const float* __restrict__ a, const float* __restrict__ hd,
                           const float* __restrict__ l1h,
                           float* __restrict__ out_hes, float* __restrict__ out_l1)
{
    __shared__ float s1s[4], s2s[4];
    int m = blockIdx.x, tid = threadIdx.x;
    float av = a[(size_t)m*BA + tid];
    float s1 = fabsf(av), s2 = av*av;
    #pragma unroll
    for (int o = 16; o; o >>= 1) {
        s1 += __shfl_xor_sync(~0u, s1, o);
        s2 += __shfl_xor_sync(~0u, s2, o);
    }
    if ((tid&31)==0) { s1s[tid>>5]=s1; s2s[tid>>5]=s2; }
    __syncthreads();
    if (tid == 0) {
        float t1 = s1s[0]+s1s[1]+s1s[2]+s1s[3];
        float t2 = s2s[0]+s2s[1]+s2s[2]+s2s[3];
        float he = hd[m]*RMC + t2*(1.0f/(BA*100.0f));
        out_l1[m] = l1h[m]*RMC + t1*(1.0f/(BA*100.0f));
        out_hes[m] = he;
        g_hes[m] = he;
        g_nsq[m] = 0.0f;
    }
}

__global__ void colnorm1_k(const float* __restrict__ NB) {
    int col = blockIdx.x*256 + threadIdx.x;
    int r0 = blockIdx.y*128;
    float s = 0.0f;
    for (int r = r0; r < r0+128; r++) {
        float v = NB[(size_t)r*BD + col];
        s = fmaf(v, v, s);
    }
    atomicAdd(&g_nsq[col], s);
}

__global__ void colnorm2_k(const float* __restrict__ NB, float* __restrict__ out) {
    int i = blockIdx.x*blockDim.x + threadIdx.x;
    if (i < ED*BD) out[i] = NB[i] * rsqrtf(g_nsq[i & (BD-1)]);
}

__global__ void copy_a_k(const float* __restrict__ a, float* __restrict__ out) {
    int i = blockIdx.x*blockDim.x + threadIdx.x;
    if (i < BD*BA) out[i] = a[i];
}

__global__ void sumI2_k(const float* __restrict__ I) {
    __shared__ float red[8];
    int tid = threadIdx.x;
    float s = 0.0f;
    for (int i = blockIdx.x*blockDim.x + tid; i < ED*BA; i += gridDim.x*blockDim.x) {
        float v = I[i];
        s = fmaf(v, v, s);
    }
    #pragma unroll
    for (int o = 16; o; o >>= 1) s += __shfl_xor_sync(~0u, s, o);
    if ((tid&31)==0) red[tid>>5] = s;
    __syncthreads();
    if (tid == 0) {
        float t = 0.0f;
        for (int i = 0; i < 8; i++) t += red[i];
        atomicAdd(&g_scal[4], t);
    }
}

__global__ void scalarfin_k(const float* __restrict__ se, const float* __restrict__ ne,
                            float* __restrict__ out_snr)
{
    float ns = se[0]*RMC + g_scal[4]*0.01f;
    out_snr[0] = ns / (ne[0]*RMC);
}

extern "C" void kernel_launch(void* const* d_in, const int* in_sizes, int n_in,
                              void* d_out, int out_size)
{
    const float* I     = (const float*)d_in[0];
    const float* basis = (const float*)d_in[1];
    const float* hd    = (const float*)d_in[2];
    const float* l1h   = (const float*)d_in[3];
    const float* se    = (const float*)d_in[4];
    const float* ne    = (const float*)d_in[5];
    float* out = (float*)d_out;

    float *BT,*It,*a,*r,*S,*T0,*T1,*NB,*G,*c;
    cudaGetSymbolAddress((void**)&BT, g_BT);
    cudaGetSymbolAddress((void**)&It, g_It);
    cudaGetSymbolAddress((void**)&a,  g_a);
    cudaGetSymbolAddress((void**)&r,  g_r);
    cudaGetSymbolAddress((void**)&S,  g_S);
    cudaGetSymbolAddress((void**)&T0, g_T0);
    cudaGetSymbolAddress((void**)&T1, g_T1);
    cudaGetSymbolAddress((void**)&NB, g_NB);
    cudaGetSymbolAddress((void**)&G,  g_G);
    cudaGetSymbolAddress((void**)&c,  g_c);

    cudaFuncSetAttribute(persist3_k, cudaFuncAttributeMaxDynamicSharedMemorySize, DYN);

    transpose_k<<<dim3(BD/32, ED/32), dim3(32,8)>>>(basis, BT, ED, BD);
    transpose_k<<<dim3(ED/32, BA/32), dim3(32,8)>>>(I, It, BA, ED);
    init_k<<<(BD*BA+255)/256, 256>>>();

    // G = B^T B [BDxBD] (+ bf16 split); c = B^T I_t [BDxBA]
    gemm_nt_k<0><<<dim3(BD/64, BD/16), 128>>>(BT, BT, G, nullptr, BD, ED);
    g2bf_k<<<(int)(((size_t)BD*BD)/256), 256>>>();
    gemm_nt_k<0><<<dim3(BA/64, BD/16), 128>>>(BT, I, c, nullptr, BA, ED);

    // S = B B^T; 6 renormalized squarings -> g_T0 = dir(S^64)
    gemm_nt_k<0><<<dim3(ED/64, ED/16), 128>>>(basis, basis, S, nullptr, ED, BD);
    copyN_k<<<(ED*ED+255)/256, 256>>>(S, T0, ED*ED);
    float* sq[2] = {T0, T1};
    for (int i = 0; i < 6; i++) {
        diagmax_k<<<1, 1024>>>(sq[0]);
        gemm_nt_k<3><<<dim3(ED/64, ED/16), 128>>>(sq[0], sq[0], sq[1], nullptr, ED, ED);
        float* t = sq[0]; sq[0] = sq[1]; sq[1] = t;
    }

    persist3_k<<<GRIDP, 256, DYN>>>(basis);

    rowstats_k<<<BD, 128>>>(a, hd, l1h, out + O_HES, out + O_L1);
    gemm_nt_k<4><<<dim3(BD/64, ED/16), 128>>>(r, a, NB, basis, BD, BA);
    colnorm1_k<<<dim3(BD/256, ED/128), 256>>>(NB);
    colnorm2_k<<<(ED*BD+255)/256, 256>>>(NB, out + O_BASIS);
    copy_a_k<<<(BD*BA+255)/256, 256>>>(a, out + O_A);
    sumI2_k<<<256, 256>>>(I);
    scalarfin_k<<<1, 1>>>(se, ne, out + O_SNR);
}

// round 11
// speedup vs baseline: 3.8663x; 1.0082x over previous
#include <cuda_runtime.h>
#include <cuda_bf16.h>
#include <cstdint>
#include <cstddef>

#define ED 1024
#define BD 2048
#define BA 128
#define NITER 500
#define LAMB_C 0.3f
#define H_C 0.005f
#define RMC 0.99f
#define LOWACT 0.001f
#define GRIDP 128

#define O_A     ((size_t)0)
#define O_BASIS ((size_t)(BD*BA))
#define O_HES   (O_BASIS + (size_t)ED*BD)
#define O_L1    (O_HES + BD)
#define O_SNR   (O_L1 + BD)

// smem: 4-stage ring, row stride 144B (72 bf16), conflict-free ldmatrix
#define GH_O 0
#define GL_O 4608
#define AH_O 9216
#define AL_O 18432
#define BUFS 28672
#define DYN  (4*BUFS)

__device__ float g_BT[(size_t)BD*ED];
__device__ float g_It[(size_t)ED*BA];
__device__ float g_a [(size_t)BD*BA];
__device__ float g_a2[(size_t)BD*BA];
__device__ float g_c [(size_t)BD*BA];
__device__ float g_G [(size_t)BD*BD];
__device__ float g_r [(size_t)ED*BA];
__device__ float g_S [(size_t)ED*ED];
__device__ float g_T0[(size_t)ED*ED];
__device__ float g_T1[(size_t)ED*ED];
__device__ float g_NB[(size_t)ED*BD];
__device__ __nv_bfloat16 g_Gh[(size_t)BD*BD];
__device__ __nv_bfloat16 g_Gl[(size_t)BD*BD];
__device__ __nv_bfloat16 g_ah0[(size_t)BD*BA];
__device__ __nv_bfloat16 g_ah1[(size_t)BD*BA];
__device__ __nv_bfloat16 g_al0[(size_t)BD*BA];
__device__ __nv_bfloat16 g_al1[(size_t)BD*BA];
__device__ __nv_bfloat16 g_Th0[(size_t)ED*ED];
__device__ __nv_bfloat16 g_Tl0[(size_t)ED*ED];
__device__ __nv_bfloat16 g_Th1[(size_t)ED*ED];
__device__ __nv_bfloat16 g_Tl1[(size_t)ED*ED];
__device__ float g_hes[BD];
__device__ float g_nsq[BD];
__device__ float g_v[ED];
__device__ float g_w[ED];
__device__ float g_scal[8];
__device__ unsigned g_cnt;
__device__ volatile unsigned g_gen;

__device__ __forceinline__ float sshrinkf(float v, float thr) {
    float t = fabsf(v) - thr;
    return t > 0.0f ? copysignf(t, v) : 0.0f;
}
__device__ __forceinline__ uint32_t smem_u32(const void* p) {
    uint32_t a;
    asm("{ .reg .u64 t; cvta.to.shared.u64 t, %1; cvt.u32.u64 %0, t; }" : "=r"(a) : "l"(p));
    return a;
}
#define LDSM4(r, ad) asm volatile( \
    "ldmatrix.sync.aligned.m8n8.x4.shared.b16 {%0,%1,%2,%3},[%4];" \
    : "=r"((r)[0]),"=r"((r)[1]),"=r"((r)[2]),"=r"((r)[3]) : "r"(ad))
#define LDSM4T(r, ad) asm volatile( \
    "ldmatrix.sync.aligned.m8n8.x4.trans.shared.b16 {%0,%1,%2,%3},[%4];" \
    : "=r"((r)[0]),"=r"((r)[1]),"=r"((r)[2]),"=r"((r)[3]) : "r"(ad))
#define MMA16816(c, a, b0, b1) asm volatile( \
    "mma.sync.aligned.m16n8k16.row.col.f32.bf16.bf16.f32 " \
    "{%0,%1,%2,%3},{%4,%5,%6,%7},{%8,%9},{%0,%1,%2,%3};" \
    : "+f"((c)[0]),"+f"((c)[1]),"+f"((c)[2]),"+f"((c)[3]) \
    : "r"((a)[0]),"r"((a)[1]),"r"((a)[2]),"r"((a)[3]),"r"(b0),"r"(b1))
#define CPA16(dst, src) asm volatile("cp.async.cg.shared.global [%0],[%1],16;" :: "r"(dst), "l"(src))
#define CPCOMMIT() asm volatile("cp.async.commit_group;" ::: "memory")
#define CPWAIT(n)  asm volatile("cp.async.wait_group %0;" :: "n"(n) : "memory")

__device__ __forceinline__ void gsync(unsigned gen) {
    __syncthreads();
    if (threadIdx.x == 0) {
        __threadfence();
        unsigned t = atomicAdd(&g_cnt, 1u);
        if (t == GRIDP - 1) { g_cnt = 0; __threadfence(); g_gen = gen; }
        else { while (g_gen < gen) { } __threadfence(); }
    }
    __syncthreads();
}

// ---- persistent: power iteration + 500 mma.sync Gram-ISTA iters + residual ----
__global__ void __launch_bounds__(256, 1) persist3_k(const float* __restrict__ basis)
{
    extern __shared__ char dsm[];
    __shared__ float red1[8], red2[8];
    __shared__ float sh_b;
    const int cta = blockIdx.x, tid = threadIdx.x;
    const int w = tid >> 5, l = tid & 31;
    unsigned gen = 0;
    const uint32_t smu = smem_u32(dsm);

    // ---- power iteration: 8 matvecs on dir(S^64) (g_T0), then S + Rayleigh ----
    for (int pi = 0; pi < 9; pi++) {
        const float* M = (pi < 8) ? g_T0 : g_S;
        {
            int rw = cta*8 + w;
            const float* mr = M + (size_t)rw*ED;
            float s = 0.f;
            for (int j = l; j < ED; j += 32) s = fmaf(mr[j], g_v[j], s);
            #pragma unroll
            for (int o = 16; o; o >>= 1) s += __shfl_xor_sync(~0u, s, o);
            if (l == 0) g_w[rw] = s;
        }
        gen++; gsync(gen);
        if (cta == 0) {
            if (pi < 8) {
                float x[4], ss = 0.f;
                #pragma unroll
                for (int i = 0; i < 4; i++) { x[i] = g_w[tid*4+i]; ss = fmaf(x[i], x[i], ss); }
                #pragma unroll
                for (int o = 16; o; o >>= 1) ss += __shfl_xor_sync(~0u, ss, o);
                if (l == 0) red1[w] = ss;
                __syncthreads();
                if (tid == 0) {
                    float t = 0.f;
                    for (int i = 0; i < 8; i++) t += red1[i];
                    sh_b = rsqrtf(t);
                }
                __syncthreads();
                float rs = sh_b;
                #pragma unroll
                for (int i = 0; i < 4; i++) g_v[tid*4+i] = x[i]*rs;
            } else {
                float d1 = 0.f, d2 = 0.f;
                #pragma unroll
                for (int i = 0; i < 4; i++) {
                    float vv = g_v[tid*4+i], ww = g_w[tid*4+i];
                    d1 = fmaf(vv, ww, d1); d2 = fmaf(vv, vv, d2);
                }
                #pragma unroll
                for (int o = 16; o; o >>= 1) {
                    d1 += __shfl_xor_sync(~0u, d1, o);
                    d2 += __shfl_xor_sync(~0u, d2, o);
                }
                if (l == 0) { red1[w] = d1; red2[w] = d2; }
                __syncthreads();
                if (tid == 0) {
                    float a = 0.f, b = 0.f;
                    for (int i = 0; i < 8; i++) { a += red1[i]; b += red2[i]; }
                    float lam = a / b;
                    g_scal[0] = lam; g_scal[1] = 1.0f/lam; g_scal[2] = LAMB_C/lam;
                }
                __syncthreads();
            }
        }
        gen++; gsync(gen);
    }

    const float eta = g_scal[1], thr = g_scal[2];
    const int mt = cta >> 1, nh = cta & 1;
    const int wm = w >> 2, wn = w & 3;
    const uint32_t adA = (uint32_t)(wm*16 + (l & 15))*144 + ((l >> 4)*16);
    const uint32_t adB = (uint32_t)((l & 7) + ((l >> 3) & 1)*8)*144 + (wn*32 + (l >> 4)*16);
    const int gur = tid >> 3, guq = tid & 7;
    const uint32_t dG  = (uint32_t)gur*144 + guq*16;
    const uint32_t dA1 = (uint32_t)(gur+32)*144 + guq*16;
    const __nv_bfloat16* GhR = g_Gh + (size_t)(mt*32 + gur)*BD + guq*8;
    const __nv_bfloat16* GlR = g_Gl + (size_t)(mt*32 + gur)*BD + guq*8;

    for (int it = 0; it < NITER; it++) {
        const int cur = it & 1;
        const float* acur = cur ? g_a2 : g_a;
        float*       anxt = cur ? g_a  : g_a2;
        const __nv_bfloat16* ahc = cur ? g_ah1 : g_ah0;
        const __nv_bfloat16* alc = cur ? g_al1 : g_al0;
        __nv_bfloat16* ahn = cur ? g_ah0 : g_ah1;
        __nv_bfloat16* aln = cur ? g_al0 : g_al1;
        const __nv_bfloat16* aH = ahc + (size_t)gur*BA + nh*64 + guq*8;
        const __nv_bfloat16* aL = alc + (size_t)gur*BA + nh*64 + guq*8;

        float acc0[4] = {0,0,0,0}, acc1[4] = {0,0,0,0};
        auto ISS = [&](int t) {
            uint32_t sb = smu + (uint32_t)(t & 3)*BUFS;
            int kc = t*64;
            CPA16(sb + GH_O + dG,  GhR + kc);
            CPA16(sb + GL_O + dG,  GlR + kc);
            CPA16(sb + AH_O + dG,  aH + (size_t)kc*BA);
            CPA16(sb + AH_O + dA1, aH + (size_t)(kc+32)*BA);
            CPA16(sb + AL_O + dG,  aL + (size_t)kc*BA);
            CPA16(sb + AL_O + dA1, aL + (size_t)(kc+32)*BA);
            CPCOMMIT();
        };
        ISS(0); ISS(1); ISS(2);

        #pragma unroll 1
        for (int t = 0; t < 32; t++) {
            if (t < 30) CPWAIT(2); else if (t == 30) CPWAIT(1); else CPWAIT(0);
            __syncthreads();
            if (t + 3 < 32) ISS(t + 3);
            const uint32_t base = smu + (uint32_t)(t & 3)*BUFS;
            #pragma unroll
            for (int kq = 0; kq < 4; kq++) {
                uint32_t fah[4], fal[4], fbh[4], fbl[4];
                LDSM4(fah, base + GH_O + kq*32 + adA);
                LDSM4(fal, base + GL_O + kq*32 + adA);
                LDSM4T(fbh, base + AH_O + kq*16*144 + adB);
                LDSM4T(fbl, base + AL_O + kq*16*144 + adB);
                MMA16816(acc0, fah, fbh[0], fbh[1]);
                MMA16816(acc1, fah, fbh[2], fbh[3]);
                MMA16816(acc0, fah, fbl[0], fbl[1]);
                MMA16816(acc1, fah, fbl[2], fbl[3]);
                MMA16816(acc0, fal, fbh[0], fbh[1]);
                MMA16816(acc1, fal, fbh[2], fbh[3]);
            }
        }

        // epilogue: shrink + fp32 store + bf16 re-split
        #pragma unroll
        for (int nt = 0; nt < 2; nt++) {
            const float* ap = nt ? acc1 : acc0;
            int gc = nh*64 + wn*16 + nt*8 + (l & 3)*2;
            #pragma unroll
            for (int rr = 0; rr < 2; rr++) {
                int gr = mt*32 + wm*16 + (l >> 2) + rr*8;
                size_t idx = (size_t)gr*BA + gc;
                float2 ao = *(const float2*)&acur[idx];
                float2 cv = *(const float2*)&g_c[idx];
                float vx = sshrinkf(ao.x + eta*(cv.x - ap[rr*2+0]), thr);
                float vy = sshrinkf(ao.y + eta*(cv.y - ap[rr*2+1]), thr);
                *(float2*)&anxt[idx] = make_float2(vx, vy);
                __nv_bfloat162 hp, lp;
                hp.x = __float2bfloat16(vx);
                hp.y = __float2bfloat16(vy);
                lp.x = __float2bfloat16(vx - __bfloat162float(hp.x));
                lp.y = __float2bfloat16(vy - __bfloat162float(hp.y));
                *(__nv_bfloat162*)&ahn[idx] = hp;
                *(__nv_bfloat162*)&aln[idx] = lp;
            }
        }
        gen++; gsync(gen);
    }

    // ---- final residual: r = It - basis*a ; warp -> one row ----
    {
        const int rw = cta*8 + w;
        float4 racc = make_float4(0.f, 0.f, 0.f, 0.f);
        float* aS = (float*)dsm;                  // [32][132]
        float* bS = (float*)(dsm + 17024);        // [8][32]
        for (int t = 0; t < 64; t++) {
            int k0 = t*32;
            float4 rv[4];
            #pragma unroll
            for (int i = 0; i < 4; i++) {
                int u = tid*4 + i, rr = u >> 5, q = u & 31;
                rv[i] = *(const float4*)&g_a[(size_t)(k0 + rr)*BA + q*4];
            }
            float bb = basis[(size_t)rw*BD + k0 + l];
            __syncthreads();
            #pragma unroll
            for (int i = 0; i < 4; i++) {
                int u = tid*4 + i, rr = u >> 5, q = u & 31;
                *(float4*)&aS[rr*132 + q*4] = rv[i];
            }
            bS[w*32 + l] = bb;
            __syncthreads();
            #pragma unroll 8
            for (int kk = 0; kk < 32; kk++) {
                float b_ = bS[w*32 + kk];
                float4 av = *(const float4*)&aS[kk*132 + l*4];
                racc.x = fmaf(b_, av.x, racc.x);
                racc.y = fmaf(b_, av.y, racc.y);
                racc.z = fmaf(b_, av.z, racc.z);
                racc.w = fmaf(b_, av.w, racc.w);
            }
        }
        float4 iv = *(const float4*)&g_It[(size_t)rw*BA + l*4];
        *(float4*)&g_r[(size_t)rw*BA + l*4] =
            make_float4(iv.x-racc.x, iv.y-racc.y, iv.z-racc.z, iv.w-racc.w);
    }
}

// ---- bf16-split squaring on mma: C = (T*T^T)*s^2, T symmetric [1024x1024] ----
__global__ void __launch_bounds__(256, 1) sqmma_k(
    const __nv_bfloat16* __restrict__ Th, const __nv_bfloat16* __restrict__ Tl,
    float* __restrict__ Cf, __nv_bfloat16* __restrict__ Ch, __nv_bfloat16* __restrict__ Cl)
{
    extern __shared__ char dsm[];
    const int tid = threadIdx.x, w = tid >> 5, l = tid & 31;
    const int nt = blockIdx.x, mt = blockIdx.y;   // grid (16, 32)
    const int wm = w >> 2, wn = w & 3;
    const uint32_t smu = smem_u32(dsm);
    const uint32_t adA = (uint32_t)(wm*16 + (l & 15))*144 + ((l >> 4)*16);
    const uint32_t adB = (uint32_t)((l & 7) + ((l >> 3) & 1)*8)*144 + (wn*32 + (l >> 4)*16);
    const int gur = tid >> 3, guq = tid & 7;
    const uint32_t dG  = (uint32_t)gur*144 + guq*16;
    const uint32_t dA1 = (uint32_t)(gur+32)*144 + guq*16;
    const __nv_bfloat16* AH = Th + (size_t)(mt*32 + gur)*ED + guq*8;
    const __nv_bfloat16* AL = Tl + (size_t)(mt*32 + gur)*ED + guq*8;
    const __nv_bfloat16* BH = Th + (size_t)gur*ED + nt*64 + guq*8;  // symmetric: rows=k
    const __nv_bfloat16* BL = Tl + (size_t)gur*ED + nt*64 + guq*8;
    float acc0[4] = {0,0,0,0}, acc1[4] = {0,0,0,0};

    auto ISS = [&](int t) {
        uint32_t sb = smu + (uint32_t)(t & 3)*BUFS;
        int kc = t*64;
        CPA16(sb + GH_O + dG,  AH + kc);
        CPA16(sb + GL_O + dG,  AL + kc);
        CPA16(sb + AH_O + dG,  BH + (size_t)kc*ED);
        CPA16(sb + AH_O + dA1, BH + (size_t)(kc+32)*ED);
        CPA16(sb + AL_O + dG,  BL + (size_t)kc*ED);
        CPA16(sb + AL_O + dA1, BL + (size_t)(kc+32)*ED);
        CPCOMMIT();
    };
    ISS(0); ISS(1); ISS(2);
    #pragma unroll 1
    for (int t = 0; t < 16; t++) {
        if (t < 14) CPWAIT(2); else if (t == 14) CPWAIT(1); else CPWAIT(0);
        __syncthreads();
        if (t + 3 < 16) ISS(t + 3);
        const uint32_t base = smu + (uint32_t)(t & 3)*BUFS;
        #pragma unroll
        for (int kq = 0; kq < 4; kq++) {
            uint32_t fah[4], fal[4], fbh[4], fbl[4];
            LDSM4(fah, base + GH_O + kq*32 + adA);
            LDSM4(fal, base + GL_O + kq*32 + adA);
            LDSM4T(fbh, base + AH_O + kq*16*144 + adB);
            LDSM4T(fbl, base + AL_O + kq*16*144 + adB);
            MMA16816(acc0, fah, fbh[0], fbh[1]);
            MMA16816(acc1, fah, fbh[2], fbh[3]);
            MMA16816(acc0, fah, fbl[0], fbl[1]);
            MMA16816(acc1, fah, fbl[2], fbl[3]);
            MMA16816(acc0, fal, fbh[0], fbh[1]);
            MMA16816(acc1, fal, fbh[2], fbh[3]);
        }
    }
    const float s2 = g_scal[3]*g_scal[3];
    #pragma unroll
    for (int ntl = 0; ntl < 2; ntl++) {
        const float* ap = ntl ? acc1 : acc0;
        int gc = nt*64 + wn*16 + ntl*8 + (l & 3)*2;
        #pragma unroll
        for (int rr = 0; rr < 2; rr++) {
            int gr = mt*32 + wm*16 + (l >> 2) + rr*8;
            size_t idx = (size_t)gr*ED + gc;
            float vx = ap[rr*2+0]*s2, vy = ap[rr*2+1]*s2;
            *(float2*)&Cf[idx] = make_float2(vx, vy);
            __nv_bfloat162 hp, lp;
            hp.x = __float2bfloat16(vx);
            hp.y = __float2bfloat16(vy);
            lp.x = __float2bfloat16(vx - __bfloat162float(hp.x));
            lp.y = __float2bfloat16(vy - __bfloat162float(hp.y));
            *(__nv_bfloat162*)&Ch[idx] = hp;
            *(__nv_bfloat162*)&Cl[idx] = lp;
        }
    }
}

// ---- NT GEMM fp32 SIMT: C[M,N] = A[M,K]*B[N,K]^T. EPI 0:store 4:basis-update ----
template<int EPI>
__global__ void __launch_bounds__(128, 2) gemm_nt_k(
    const float* __restrict__ A, const float* __restrict__ Bm,
    float* __restrict__ C, const float* __restrict__ Aux, int Nh, int Kh)
{
    __shared__ float As[2][64][18];
    __shared__ float Bs[2][64][68];
    const int tid = threadIdx.x;
    const int tx = tid & 15, ty = tid >> 4;
    const float* Ab = A + (size_t)blockIdx.y * 16 * Kh;
    const float* Bb = Bm + (size_t)blockIdx.x * 64 * Kh;
    const int ar0 = tid >> 4, ar1 = (tid + 128) >> 4, ak = (tid & 15) * 4;
    float4 ra0, ra1, rb[8];
    float acc[2][4] = {{0,0,0,0},{0,0,0,0}};

    ra0 = *(const float4*)(Ab + (size_t)ar0*Kh + ak);
    ra1 = *(const float4*)(Ab + (size_t)ar1*Kh + ak);
    #pragma unroll
    for (int i = 0; i < 8; i++) {
        int q = tid + i*128;
        rb[i] = *(const float4*)(Bb + (size_t)(q>>4)*Kh + (q&15)*4);
    }
    As[0][ak+0][ar0]=ra0.x; As[0][ak+1][ar0]=ra0.y; As[0][ak+2][ar0]=ra0.z; As[0][ak+3][ar0]=ra0.w;
    As[0][ak+0][ar1]=ra1.x; As[0][ak+1][ar1]=ra1.y; As[0][ak+2][ar1]=ra1.z; As[0][ak+3][ar1]=ra1.w;
    #pragma unroll
    for (int i = 0; i < 8; i++) {
        int q = tid + i*128; int n = q>>4; int kq = (q&15)*4;
        Bs[0][kq+0][n]=rb[i].x; Bs[0][kq+1][n]=rb[i].y; Bs[0][kq+2][n]=rb[i].z; Bs[0][kq+3][n]=rb[i].w;
    }
    const int T = Kh >> 6;
    for (int t = 0; t < T; t++) {
        __syncthreads();
        if (t + 1 < T) {
            int k0 = (t+1) * 64;
            ra0 = *(const float4*)(Ab + (size_t)ar0*Kh + k0 + ak);
            ra1 = *(const float4*)(Ab + (size_t)ar1*Kh + k0 + ak);
            #pragma unroll
            for (int i = 0; i < 8; i++) {
                int q = tid + i*128;
                rb[i] = *(const float4*)(Bb + (size_t)(q>>4)*Kh + k0 + (q&15)*4);
            }
        }
        const int buf = t & 1;
        #pragma unroll
        for (int kk = 0; kk < 64; kk++) {
            float2 av = *(const float2*)&As[buf][kk][ty*2];
            float4 bv = *(const float4*)&Bs[buf][kk][tx*4];
            acc[0][0]=fmaf(av.x,bv.x,acc[0][0]); acc[0][1]=fmaf(av.x,bv.y,acc[0][1]);
            acc[0][2]=fmaf(av.x,bv.z,acc[0][2]); acc[0][3]=fmaf(av.x,bv.w,acc[0][3]);
            acc[1][0]=fmaf(av.y,bv.x,acc[1][0]); acc[1][1]=fmaf(av.y,bv.y,acc[1][1]);
            acc[1][2]=fmaf(av.y,bv.z,acc[1][2]); acc[1][3]=fmaf(av.y,bv.w,acc[1][3]);
        }
        if (t + 1 < T) {
            const int nb = (t+1) & 1;
            As[nb][ak+0][ar0]=ra0.x; As[nb][ak+1][ar0]=ra0.y; As[nb][ak+2][ar0]=ra0.z; As[nb][ak+3][ar0]=ra0.w;
            As[nb][ak+0][ar1]=ra1.x; As[nb][ak+1][ar1]=ra1.y; As[nb][ak+2][ar1]=ra1.z; As[nb][ak+3][ar1]=ra1.w;
            #pragma unroll
            for (int i = 0; i < 8; i++) {
                int q = tid + i*128; int n = q>>4; int kq = (q&15)*4;
                Bs[nb][kq+0][n]=rb[i].x; Bs[nb][kq+1][n]=rb[i].y; Bs[nb][kq+2][n]=rb[i].z; Bs[nb][kq+3][n]=rb[i].w;
            }
        }
    }
    const int gm = blockIdx.y*16 + ty*2;
    const int gn = blockIdx.x*64 + tx*4;
    if (EPI == 0) {
        #pragma unroll
        for (int mi = 0; mi < 2; mi++)
            *(float4*)(C + (size_t)(gm+mi)*Nh + gn) =
                make_float4(acc[mi][0],acc[mi][1],acc[mi][2],acc[mi][3]);
    } else {
        #pragma unroll
        for (int mi = 0; mi < 2; mi++)
            #pragma unroll
            for (int ni = 0; ni < 4; ni++) {
                int col = gn + ni;
                C[(size_t)(gm+mi)*Nh + col] = Aux[(size_t)(gm+mi)*Nh + col] +
                    (H_C/(float)BA) * acc[mi][ni] / (g_hes[col] + LOWACT);
            }
    }
}

__global__ void transpose_k(const float* __restrict__ in, float* __restrict__ out,
                            int rows, int cols)
{
    __shared__ float sm[32][33];
    int bx = blockIdx.x*32, by = blockIdx.y*32;
    int tx = threadIdx.x, ty = threadIdx.y;
    #pragma unroll
    for (int j = 0; j < 32; j += 8)
        sm[ty+j][tx] = in[(size_t)(by+ty+j)*cols + bx+tx];
    __syncthreads();
    #pragma unroll
    for (int j = 0; j < 32; j += 8)
        out[(size_t)(bx+ty+j)*rows + by+tx] = sm[tx][ty+j];
}

__global__ void init_k() {
    int idx = blockIdx.x*256 + threadIdx.x;
    if (idx < BD*BA) {
        g_a[idx] = 0.0f;
        g_ah0[idx] = __float2bfloat16(0.0f);
        g_al0[idx] = __float2bfloat16(0.0f);
    }
    if (idx < ED) g_v[idx] = 1.0f;
    if (idx == 0) { g_scal[4] = 0.0f; g_cnt = 0; g_gen = 0; }
}

__global__ void g2bf_k() {
    size_t idx = (size_t)blockIdx.x*256 + threadIdx.x;
    float g = g_G[idx];
    __nv_bfloat16 h = __float2bfloat16(g);
    g_Gh[idx] = h;
    g_Gl[idx] = __float2bfloat16(g - __bfloat162float(h));
}

__global__ void splitf_k(const float* __restrict__ in, __nv_bfloat16* __restrict__ h,
                         __nv_bfloat16* __restrict__ lo, int n)
{
    int i = blockIdx.x*256 + threadIdx.x;
    if (i < n) {
        float g = in[i];
        __nv_bfloat16 hh = __float2bfloat16(g);
        h[i] = hh;
        lo[i] = __float2bfloat16(g - __bfloat162float(hh));
    }
}

__global__ void copyN_k(const float* __restrict__ in, float* __restrict__ out, int n) {
    int i = blockIdx.x*256 + threadIdx.x;
    if (i < n) out[i] = in[i];
}

__global__ void diagmax_k(const float* __restrict__ T) {
    __shared__ float red[32];
    int tid = threadIdx.x;
    float m = fabsf(T[(size_t)tid*ED + tid]);
    #pragma unroll
    for (int o = 16; o; o >>= 1) m = fmaxf(m, __shfl_xor_sync(~0u, m, o));
    if ((tid&31)==0) red[tid>>5] = m;
    __syncthreads();
    if (tid < 32) {
        float mm = red[tid];
        #pragma unroll
        for (int o = 16; o; o >>= 1) mm = fmaxf(mm, __shfl_xor_sync(~0u, mm, o));
        if (tid == 0) g_scal[3] = 1.0f / mm;
    }
}

__global__ void rowstats_k(const float* __restrict__ a, const float* __restrict__ hd,
                           const float* __restrict__ l1h,
                           float* __restrict__ out_hes, float* __restrict__ out_l1)
{
    __shared__ float s1s[4], s2s[4];
    int m = blockIdx.x, tid = threadIdx.x;
    float av = a[(size_t)m*BA + tid];
    float s1 = fabsf(av), s2 = av*av;
    #pragma unroll
    for (int o = 16; o; o >>= 1) {
        s1 += __shfl_xor_sync(~0u, s1, o);
        s2 += __shfl_xor_sync(~0u, s2, o);
    }
    if ((tid&31)==0) { s1s[tid>>5]=s1; s2s[tid>>5]=s2; }
    __syncthreads();
    if (tid == 0) {
        float t1 = s1s[0]+s1s[1]+s1s[2]+s1s[3];
        float t2 = s2s[0]+s2s[1]+s2s[2]+s2s[3];
        float he = hd[m]*RMC + t2*(1.0f/(BA*100.0f));
        out_l1[m] = l1h[m]*RMC + t1*(1.0f/(BA*100.0f));
        out_hes[m] = he;
        g_hes[m] = he;
        g_nsq[m] = 0.0f;
    }
}

__global__ void colnorm1_k(const float* __restrict__ NB) {
    int col = blockIdx.x*256 + threadIdx.x;
    int r0 = blockIdx.y*128;
    float s = 0.0f;
    for (int r = r0; r < r0+128; r++) {
        float v = NB[(size_t)r*BD + col];
        s = fmaf(v, v, s);
    }
    atomicAdd(&g_nsq[col], s);
}

__global__ void colnorm2_k(const float* __restrict__ NB, float* __restrict__ out) {
    int i = blockIdx.x*blockDim.x + threadIdx.x;
    if (i < ED*BD) out[i] = NB[i] * rsqrtf(g_nsq[i & (BD-1)]);
}

__global__ void copy_a_k(const float* __restrict__ a, float* __restrict__ out) {
    int i = blockIdx.x*blockDim.x + threadIdx.x;
    if (i < BD*BA) out[i] = a[i];
}

__global__ void sumI2_k(const float* __restrict__ I) {
    __shared__ float red[8];
    int tid = threadIdx.x;
    float s = 0.0f;
    for (int i = blockIdx.x*blockDim.x + tid; i < ED*BA; i += gridDim.x*blockDim.x) {
        float v = I[i];
        s = fmaf(v, v, s);
    }
    #pragma unroll
    for (int o = 16; o; o >>= 1) s += __shfl_xor_sync(~0u, s, o);
    if ((tid&31)==0) red[tid>>5] = s;
    __syncthreads();
    if (tid == 0) {
        float t = 0.0f;
        for (int i = 0; i < 8; i++) t += red[i];
        atomicAdd(&g_scal[4], t);
    }
}

__global__ void scalarfin_k(const float* __restrict__ se, const float* __restrict__ ne,
                            float* __restrict__ out_snr)
{
    float ns = se[0]*RMC + g_scal[4]*0.01f;
    out_snr[0] = ns / (ne[0]*RMC);
}

extern "C" void kernel_launch(void* const* d_in, const int* in_sizes, int n_in,
                              void* d_out, int out_size)
{
    const float* I     = (const float*)d_in[0];
    const float* basis = (const float*)d_in[1];
    const float* hd    = (const float*)d_in[2];
    const float* l1h   = (const float*)d_in[3];
    const float* se    = (const float*)d_in[4];
    const float* ne    = (const float*)d_in[5];
    float* out = (float*)d_out;

    float *BT,*It,*a,*r,*S,*T0,*T1,*NB,*G,*c;
    __nv_bfloat16 *Th0,*Tl0,*Th1,*Tl1;
    cudaGetSymbolAddress((void**)&BT, g_BT);
    cudaGetSymbolAddress((void**)&It, g_It);
    cudaGetSymbolAddress((void**)&a,  g_a);
    cudaGetSymbolAddress((void**)&r,  g_r);
    cudaGetSymbolAddress((void**)&S,  g_S);
    cudaGetSymbolAddress((void**)&T0, g_T0);
    cudaGetSymbolAddress((void**)&T1, g_T1);
    cudaGetSymbolAddress((void**)&NB, g_NB);
    cudaGetSymbolAddress((void**)&G,  g_G);
    cudaGetSymbolAddress((void**)&c,  g_c);
    cudaGetSymbolAddress((void**)&Th0, g_Th0);
    cudaGetSymbolAddress((void**)&Tl0, g_Tl0);
    cudaGetSymbolAddress((void**)&Th1, g_Th1);
    cudaGetSymbolAddress((void**)&Tl1, g_Tl1);

    cudaFuncSetAttribute(persist3_k, cudaFuncAttributeMaxDynamicSharedMemorySize, DYN);
    cudaFuncSetAttribute(sqmma_k,    cudaFuncAttributeMaxDynamicSharedMemorySize, DYN);

    transpose_k<<<dim3(BD/32, ED/32), dim3(32,8)>>>(basis, BT, ED, BD);
    transpose_k<<<dim3(ED/32, BA/32), dim3(32,8)>>>(I, It, BA, ED);
    init_k<<<(BD*BA+255)/256, 256>>>();

    // G = B^T B [BDxBD] fp32 (+ bf16 split); c = B^T I_t [BDxBA]
    gemm_nt_k<0><<<dim3(BD/64, BD/16), 128>>>(BT, BT, G, nullptr, BD, ED);
    g2bf_k<<<(int)(((size_t)BD*BD)/256), 256>>>();
    gemm_nt_k<0><<<dim3(BA/64, BD/16), 128>>>(BT, I, c, nullptr, BA, ED);

    // S = B B^T fp32; 6 renormalized squarings on mma (split bf16) -> g_T0 = dir(S^64)
    gemm_nt_k<0><<<dim3(ED/64, ED/16), 128>>>(basis, basis, S, nullptr, ED, BD);
    copyN_k<<<(ED*ED+255)/256, 256>>>(S, T0, ED*ED);
    splitf_k<<<(ED*ED+255)/256, 256>>>(S, Th0, Tl0, ED*ED);
    float* fp[2] = {T0, T1};
    __nv_bfloat16* hp[2] = {Th0, Th1};
    __nv_bfloat16* lp[2] = {Tl0, Tl1};
    for (int i = 0; i < 6; i++) {
        diagmax_k<<<1, 1024>>>(fp[0]);
        sqmma_k<<<dim3(16, 32), 256, DYN>>>(hp[0], lp[0], fp[1], hp[1], lp[1]);
        float* tf = fp[0]; fp[0] = fp[1]; fp[1] = tf;
        __nv_bfloat16* th = hp[0]; hp[0] = hp[1]; hp[1] = th;
        __nv_bfloat16* tl = lp[0]; lp[0] = lp[1]; lp[1] = tl;
    }
    // after 6 swaps fp[0] == T0 (holds dir(S^64) in fp32)

    persist3_k<<<GRIDP, 256, DYN>>>(basis);

    rowstats_k<<<BD, 128>>>(a, hd, l1h, out + O_HES, out + O_L1);
    gemm_nt_k<4><<<dim3(BD/64, ED/16), 128>>>(r, a, NB, basis, BD, BA);
    colnorm1_k<<<dim3(BD/256, ED/128), 256>>>(NB);
    colnorm2_k<<<(ED*BD+255)/256, 256>>>(NB, out + O_BASIS);
    copy_a_k<<<(BD*BA+255)/256, 256>>>(a, out + O_A);
    sumI2_k<<<256, 256>>>(I);
    scalarfin_k<<<1, 1>>>(se, ne, out + O_SNR);
}